// round 1
// baseline (speedup 1.0000x reference)
#include <cuda_runtime.h>

// TrajectoryGRU: B=16384, T=50, I=6, H=128, FUT=30
// Persistent-per-CTA fused GRU: each CTA owns ROWS batch rows through all
// T+FUT steps. w_hh rows live in registers (thread o holds w_hh[o][0:128]),
// hidden state + gate pre-activations in SMEM, broadcast LDS feeds FMA.

#define BSZ   16384
#define TT    50
#define II    6
#define HH    128
#define GG    384        // 3*H
#define FUTN  30
#define ROWS  16         // batch rows per CTA (BSZ/ROWS = 1024 CTAs)
#define RPAD  20         // padded row stride: 20*tid mod 32 covers all banks
#define NTHREADS 384

struct Smem {
  float h [HH][RPAD];          // hidden state, [j][r]
  float gi[GG][RPAD];          // input-gate preacts
  float gh[GG][RPAD];          // hidden-gate preacts
  float x [II][RPAD];          // current input, [i][r]
  float a [ROWS][HH + 2];      // relu hidden of head, [r][j] (+2 pad)
  float w1t[HH][HH];           // w1 transposed: w1t[k][j] = w1[j][k]
  float w2s[II][HH + 2];       // w2 padded
  float b1s[HH];
  float b2s[II];
};

__device__ __forceinline__ float sigf(float v) {
  return 1.0f / (1.0f + __expf(-v));
}
__device__ __forceinline__ float tanhfast(float v) {
  // tanh(|v|) = (1-e)/(1+e), e = exp(-2|v|); sign-restored. Avoids exp overflow.
  float av = fabsf(v);
  float e  = __expf(-2.0f * av);
  float t  = (1.0f - e) / (1.0f + e);
  return copysignf(t, v);
}

__global__ void __launch_bounds__(NTHREADS, 1)
gru_traj_kernel(const float* __restrict__ history,
                const float* __restrict__ w_ih,
                const float* __restrict__ w_hh,
                const float* __restrict__ b_ih,
                const float* __restrict__ b_hh,
                const float* __restrict__ w1,
                const float* __restrict__ b1,
                const float* __restrict__ w2,
                const float* __restrict__ b2,
                float* __restrict__ out)
{
  extern __shared__ char smem_raw[];
  Smem& sm = *reinterpret_cast<Smem*>(smem_raw);
  const int tid  = threadIdx.x;           // 0..383 == gate index o
  const int row0 = blockIdx.x * ROWS;

  // ---- weight-stationary registers: w_hh row `tid` (128 regs) ----
  float wreg[HH];
  {
    const float4* w4 = reinterpret_cast<const float4*>(w_hh) + tid * (HH / 4);
    #pragma unroll
    for (int k4 = 0; k4 < HH / 4; k4++) {
      float4 v = w4[k4];
      wreg[4*k4+0] = v.x; wreg[4*k4+1] = v.y;
      wreg[4*k4+2] = v.z; wreg[4*k4+3] = v.w;
    }
  }
  float wi[II];
  #pragma unroll
  for (int i = 0; i < II; i++) wi[i] = w_ih[tid * II + i];
  const float bi_r = b_ih[tid];
  const float bh_r = b_hh[tid];

  // ---- shared weights for the decoder head ----
  for (int idx = tid; idx < HH * HH; idx += NTHREADS) {
    int j = idx >> 7, k = idx & (HH - 1);
    sm.w1t[k][j] = w1[idx];               // transpose on the fly
  }
  for (int idx = tid; idx < II * HH; idx += NTHREADS)
    sm.w2s[idx >> 7][idx & (HH - 1)] = w2[idx];
  if (tid < HH) sm.b1s[tid] = b1[tid];
  if (tid < II) sm.b2s[tid] = b2[tid];

  // ---- h = 0 ----
  for (int idx = tid; idx < HH * RPAD; idx += NTHREADS)
    (&sm.h[0][0])[idx] = 0.0f;

  for (int t = 0; t < TT + FUTN; t++) {
    // encoder input load (decoder reuses x written by the head; first decoder
    // step reuses x of t = TT-1 == history[:, -1], matching the reference)
    if (t < TT) {
      for (int idx = tid; idx < II * ROWS; idx += NTHREADS) {
        int r = idx / II, i = idx - r * II;
        sm.x[i][r] = history[(size_t)(row0 + r) * (TT * II) + t * II + i];
      }
    }
    __syncthreads();   // S1: x and h visible

    // ---- gate GEMMs: gi[o][:] and gh[o][:] for ROWS rows, 4 at a time ----
    #pragma unroll
    for (int rb = 0; rb < ROWS; rb += 4) {
      float4 g;
      g.x = g.y = g.z = g.w = bi_r;
      #pragma unroll
      for (int i = 0; i < II; i++) {
        float  wv = wi[i];
        float4 xv = *reinterpret_cast<const float4*>(&sm.x[i][rb]);
        g.x = fmaf(wv, xv.x, g.x); g.y = fmaf(wv, xv.y, g.y);
        g.z = fmaf(wv, xv.z, g.z); g.w = fmaf(wv, xv.w, g.w);
      }
      *reinterpret_cast<float4*>(&sm.gi[tid][rb]) = g;

      g.x = g.y = g.z = g.w = bh_r;
      #pragma unroll
      for (int k = 0; k < HH; k++) {
        float  wv = wreg[k];
        float4 hv = *reinterpret_cast<const float4*>(&sm.h[k][rb]); // broadcast
        g.x = fmaf(wv, hv.x, g.x); g.y = fmaf(wv, hv.y, g.y);
        g.z = fmaf(wv, hv.z, g.z); g.w = fmaf(wv, hv.w, g.w);
      }
      *reinterpret_cast<float4*>(&sm.gh[tid][rb]) = g;
    }
    __syncthreads();   // S2: gates ready

    // ---- gate combine: h' = (1-z)*n + z*h ----
    for (int idx = tid; idx < HH * ROWS; idx += NTHREADS) {
      int j = idx >> 4, r = idx & (ROWS - 1);
      float rg = sigf(sm.gi[j][r]        + sm.gh[j][r]);
      float zg = sigf(sm.gi[j + HH][r]   + sm.gh[j + HH][r]);
      float ng = tanhfast(fmaf(rg, sm.gh[j + 2*HH][r], sm.gi[j + 2*HH][r]));
      float ho = sm.h[j][r];
      sm.h[j][r] = fmaf(zg, ho - ng, ng);
    }
    __syncthreads();   // S3: h' ready

    // ---- decoder head: x = relu(h@w1^T + b1) @ w2^T + b2 ----
    if (t >= TT) {
      const int j = tid & (HH - 1);
      for (int r = tid >> 7; r < ROWS; r += 3) {
        float acc = sm.b1s[j];
        #pragma unroll
        for (int k = 0; k < HH; k++)
          acc = fmaf(sm.w1t[k][j], sm.h[k][r], acc);  // w1t conflict-free, h broadcast
        sm.a[r][j] = fmaxf(acc, 0.0f);
      }
      __syncthreads(); // S4: a ready

      if (tid < II * ROWS) {     // 96 threads
        int i = tid >> 4, r = tid & (ROWS - 1);
        float acc = sm.b2s[i];
        #pragma unroll
        for (int k = 0; k < HH; k++)
          acc = fmaf(sm.w2s[i][k], sm.a[r][k], acc);
        sm.x[i][r] = acc;        // feeds next GRU step (after next S1)
        out[(size_t)(row0 + r) * (FUTN * II) + (t - TT) * II + i] = acc;
      }
      // no sync needed: next-iteration S1 orders sm.x/sm.a reuse
    }
  }
}

extern "C" void kernel_launch(void* const* d_in, const int* in_sizes, int n_in,
                              void* d_out, int out_size) {
  const float* history = (const float*)d_in[0];
  const float* w_ih    = (const float*)d_in[1];
  const float* w_hh    = (const float*)d_in[2];
  const float* b_ih    = (const float*)d_in[3];
  const float* b_hh    = (const float*)d_in[4];
  const float* w1      = (const float*)d_in[5];
  const float* b1      = (const float*)d_in[6];
  const float* w2      = (const float*)d_in[7];
  const float* b2      = (const float*)d_in[8];
  float* out = (float*)d_out;

  const int smem = (int)sizeof(Smem);   // ~150 KB -> needs opt-in
  cudaFuncSetAttribute(gru_traj_kernel,
                       cudaFuncAttributeMaxDynamicSharedMemorySize, smem);
  gru_traj_kernel<<<BSZ / ROWS, NTHREADS, smem>>>(
      history, w_ih, w_hh, b_ih, b_hh, w1, b1, w2, b2, out);
}

// round 2
// speedup vs baseline: 1.3793x; 1.3793x over previous
#include <cuda_runtime.h>

// TrajectoryGRU: B=16384, T=50, I=6, H=128, FUT=30
// Split-K persistent GRU: 768 threads/CTA. Thread (o, half) holds 64 of
// w_hh[o]'s 128 weights in registers, computes a partial gate sum for 16
// batch rows into SMEM; combine stage sums the halves. 24 warps/SM.

#define BSZ   16384
#define TT    50
#define II    6
#define HH    128
#define GG    384        // 3*H
#define FUTN  30
#define ROWS  16         // batch rows per CTA
#define RPAD  20         // 20*o mod 32 covers all banks for STS.128
#define NT    768
#define KH    64         // k-half length

struct Smem {
  float h  [HH][RPAD];          // hidden state [j][r]
  float gi [GG][RPAD];          // input-gate preacts (incl b_ih)
  float ghp[2][GG][RPAD];       // partial hidden-gate preacts (half0 incl b_hh)
  float x  [II][RPAD];          // current input
  float a  [ROWS][HH + 2];      // relu(h@w1^T+b1)
  float w1t[HH][HH];            // w1 transposed
  float w2s[II][HH + 2];
  float wihs[GG][II];
  float b1s[HH];
  float b2s[II];
};

__device__ __forceinline__ float sigf(float v) {
  return 1.0f / (1.0f + __expf(-v));
}
__device__ __forceinline__ float tanhfast(float v) {
  float av = fabsf(v);
  float e  = __expf(-2.0f * av);
  float t  = (1.0f - e) / (1.0f + e);
  return copysignf(t, v);
}

__global__ void __launch_bounds__(NT, 1)
gru_traj_kernel(const float* __restrict__ history,
                const float* __restrict__ w_ih,
                const float* __restrict__ w_hh,
                const float* __restrict__ b_ih,
                const float* __restrict__ b_hh,
                const float* __restrict__ w1,
                const float* __restrict__ b1,
                const float* __restrict__ w2,
                const float* __restrict__ b2,
                float* __restrict__ out)
{
  extern __shared__ char smem_raw[];
  Smem& sm = *reinterpret_cast<Smem*>(smem_raw);
  const int tid  = threadIdx.x;           // 0..767
  const int half = (tid >= GG) ? 1 : 0;
  const int o    = tid - half * GG;       // gate index 0..383
  const int row0 = blockIdx.x * ROWS;

  // ---- weight-stationary registers: half of w_hh row o (64 regs) ----
  float wreg[KH];
  {
    const float4* w4 =
        reinterpret_cast<const float4*>(w_hh + o * HH + half * KH);
    #pragma unroll
    for (int k4 = 0; k4 < KH / 4; k4++) {
      float4 v = w4[k4];
      wreg[4*k4+0] = v.x; wreg[4*k4+1] = v.y;
      wreg[4*k4+2] = v.z; wreg[4*k4+3] = v.w;
    }
  }
  const float bh_r = half ? 0.0f : b_hh[o];
  const float bi_r = b_ih[o];             // used by half 0 only

  // ---- shared weights ----
  for (int idx = tid; idx < HH * HH; idx += NT) {
    int j = idx >> 7, k = idx & (HH - 1);
    sm.w1t[k][j] = w1[idx];
  }
  for (int idx = tid; idx < II * HH; idx += NT)
    sm.w2s[idx >> 7][idx & (HH - 1)] = w2[idx];
  for (int idx = tid; idx < GG * II; idx += NT)
    sm.wihs[idx / II][idx % II] = w_ih[idx];
  if (tid < HH) sm.b1s[tid] = b1[tid];
  if (tid < II) sm.b2s[tid] = b2[tid];

  // ---- h = 0 ----
  for (int idx = tid; idx < HH * RPAD; idx += NT)
    (&sm.h[0][0])[idx] = 0.0f;

  for (int t = 0; t < TT + FUTN; t++) {
    if (t < TT) {
      if (tid < II * ROWS) {
        int r = tid / II, i = tid - r * II;
        sm.x[i][r] = history[(size_t)(row0 + r) * (TT * II) + t * II + i];
      }
    }
    __syncthreads();   // S1: x and h visible

    // ---- partial gh GEMM: ghp[half][o][:] ----
    const float* hbase = &sm.h[half * KH][0];
    #pragma unroll 1
    for (int rb = 0; rb < ROWS; rb += 4) {
      float4 g;
      g.x = g.y = g.z = g.w = bh_r;
      #pragma unroll
      for (int k = 0; k < KH; k++) {
        float  wv = wreg[k];
        float4 hv = *reinterpret_cast<const float4*>(hbase + k * RPAD + rb);
        g.x = fmaf(wv, hv.x, g.x); g.y = fmaf(wv, hv.y, g.y);
        g.z = fmaf(wv, hv.z, g.z); g.w = fmaf(wv, hv.w, g.w);
      }
      *reinterpret_cast<float4*>(&sm.ghp[half][o][rb]) = g;
    }
    // ---- gi (half 0 only; tiny: 6 FMAs per row) ----
    if (!half) {
      #pragma unroll 1
      for (int rb = 0; rb < ROWS; rb += 4) {
        float4 g;
        g.x = g.y = g.z = g.w = bi_r;
        #pragma unroll
        for (int i = 0; i < II; i++) {
          float  wv = sm.wihs[o][i];
          float4 xv = *reinterpret_cast<const float4*>(&sm.x[i][rb]);
          g.x = fmaf(wv, xv.x, g.x); g.y = fmaf(wv, xv.y, g.y);
          g.z = fmaf(wv, xv.z, g.z); g.w = fmaf(wv, xv.w, g.w);
        }
        *reinterpret_cast<float4*>(&sm.gi[o][rb]) = g;
      }
    }
    __syncthreads();   // S2: gates ready

    // ---- gate combine ----
    for (int idx = tid; idx < HH * ROWS; idx += NT) {
      int j = idx >> 4, r = idx & (ROWS - 1);
      float gr = sm.gi[j][r]        + sm.ghp[0][j][r]        + sm.ghp[1][j][r];
      float gz = sm.gi[j +   HH][r] + sm.ghp[0][j +   HH][r] + sm.ghp[1][j +   HH][r];
      float hn =                      sm.ghp[0][j + 2*HH][r] + sm.ghp[1][j + 2*HH][r];
      float rg = sigf(gr);
      float zg = sigf(gz);
      float ng = tanhfast(fmaf(rg, hn, sm.gi[j + 2*HH][r]));
      float ho = sm.h[j][r];
      sm.h[j][r] = fmaf(zg, ho - ng, ng);
    }
    __syncthreads();   // S3: h' ready

    // ---- decoder head ----
    if (t >= TT) {
      const int j   = tid & (HH - 1);
      const int grp = tid >> 7;            // 0..5
      for (int r = grp; r < ROWS; r += 6) {
        float acc = sm.b1s[j];
        #pragma unroll 8
        for (int k = 0; k < HH; k++)
          acc = fmaf(sm.w1t[k][j], sm.h[k][r], acc);
        sm.a[r][j] = fmaxf(acc, 0.0f);
      }
      __syncthreads(); // S4: a ready

      if (tid < II * ROWS) {   // 96 threads
        int i = tid >> 4, r = tid & (ROWS - 1);
        float acc = sm.b2s[i];
        #pragma unroll 8
        for (int k = 0; k < HH; k++)
          acc = fmaf(sm.w2s[i][k], sm.a[r][k], acc);
        sm.x[i][r] = acc;
        out[(size_t)(row0 + r) * (FUTN * II) + (t - TT) * II + i] = acc;
      }
      // next-iteration S1 orders sm.x reuse
    }
  }
}

extern "C" void kernel_launch(void* const* d_in, const int* in_sizes, int n_in,
                              void* d_out, int out_size) {
  const float* history = (const float*)d_in[0];
  const float* w_ih    = (const float*)d_in[1];
  const float* w_hh    = (const float*)d_in[2];
  const float* b_ih    = (const float*)d_in[3];
  const float* b_hh    = (const float*)d_in[4];
  const float* w1      = (const float*)d_in[5];
  const float* b1      = (const float*)d_in[6];
  const float* w2      = (const float*)d_in[7];
  const float* b2      = (const float*)d_in[8];
  float* out = (float*)d_out;

  const int smem = (int)sizeof(Smem);   // ~190 KB
  cudaFuncSetAttribute(gru_traj_kernel,
                       cudaFuncAttributeMaxDynamicSharedMemorySize, smem);
  gru_traj_kernel<<<BSZ / ROWS, NT, smem>>>(
      history, w_ih, w_hh, b_ih, b_hh, w1, b1, w2, b2, out);
}

// round 3
// speedup vs baseline: 1.3797x; 1.0003x over previous
#include <cuda_runtime.h>

// TrajectoryGRU: B=16384, T=50, I=6, H=128, FUT=30
// Split-K persistent GRU: 768 threads/CTA. Thread (o, half) holds 64 of
// w_hh[o]'s 128 weights in registers, computes a partial gate sum for 16
// batch rows into SMEM; combine stage sums the halves. 24 warps/SM.

#define BSZ   16384
#define TT    50
#define II    6
#define HH    128
#define GG    384        // 3*H
#define FUTN  30
#define ROWS  16         // batch rows per CTA
#define RPAD  20         // 20*o mod 32 covers all banks for STS.128
#define NT    768
#define KH    64         // k-half length

struct Smem {
  float h  [HH][RPAD];          // hidden state [j][r]
  float gi [GG][RPAD];          // input-gate preacts (incl b_ih)
  float ghp[2][GG][RPAD];       // partial hidden-gate preacts (half0 incl b_hh)
  float x  [II][RPAD];          // current input
  float a  [ROWS][HH + 2];      // relu(h@w1^T+b1)
  float w1t[HH][HH];            // w1 transposed
  float w2s[II][HH + 2];
  float wihs[GG][II];
  float b1s[HH];
  float b2s[II];
};

__device__ __forceinline__ float sigf(float v) {
  return 1.0f / (1.0f + __expf(-v));
}
__device__ __forceinline__ float tanhfast(float v) {
  float av = fabsf(v);
  float e  = __expf(-2.0f * av);
  float t  = (1.0f - e) / (1.0f + e);
  return copysignf(t, v);
}

__global__ void __launch_bounds__(NT, 1)
gru_traj_kernel(const float* __restrict__ history,
                const float* __restrict__ w_ih,
                const float* __restrict__ w_hh,
                const float* __restrict__ b_ih,
                const float* __restrict__ b_hh,
                const float* __restrict__ w1,
                const float* __restrict__ b1,
                const float* __restrict__ w2,
                const float* __restrict__ b2,
                float* __restrict__ out)
{
  extern __shared__ char smem_raw[];
  Smem& sm = *reinterpret_cast<Smem*>(smem_raw);
  const int tid  = threadIdx.x;           // 0..767
  const int half = (tid >= GG) ? 1 : 0;
  const int o    = tid - half * GG;       // gate index 0..383
  const int row0 = blockIdx.x * ROWS;

  // ---- weight-stationary registers: half of w_hh row o (64 regs) ----
  float wreg[KH];
  {
    const float4* w4 =
        reinterpret_cast<const float4*>(w_hh + o * HH + half * KH);
    #pragma unroll
    for (int k4 = 0; k4 < KH / 4; k4++) {
      float4 v = w4[k4];
      wreg[4*k4+0] = v.x; wreg[4*k4+1] = v.y;
      wreg[4*k4+2] = v.z; wreg[4*k4+3] = v.w;
    }
  }
  const float bh_r = half ? 0.0f : b_hh[o];
  const float bi_r = b_ih[o];             // used by half 0 only

  // ---- shared weights ----
  for (int idx = tid; idx < HH * HH; idx += NT) {
    int j = idx >> 7, k = idx & (HH - 1);
    sm.w1t[k][j] = w1[idx];
  }
  for (int idx = tid; idx < II * HH; idx += NT)
    sm.w2s[idx >> 7][idx & (HH - 1)] = w2[idx];
  for (int idx = tid; idx < GG * II; idx += NT)
    sm.wihs[idx / II][idx % II] = w_ih[idx];
  if (tid < HH) sm.b1s[tid] = b1[tid];
  if (tid < II) sm.b2s[tid] = b2[tid];

  // ---- h = 0 ----
  for (int idx = tid; idx < HH * RPAD; idx += NT)
    (&sm.h[0][0])[idx] = 0.0f;

  for (int t = 0; t < TT + FUTN; t++) {
    if (t < TT) {
      if (tid < II * ROWS) {
        int r = tid / II, i = tid - r * II;
        sm.x[i][r] = history[(size_t)(row0 + r) * (TT * II) + t * II + i];
      }
    }
    __syncthreads();   // S1: x and h visible

    // ---- partial gh GEMM: ghp[half][o][:] ----
    const float* hbase = &sm.h[half * KH][0];
    #pragma unroll 1
    for (int rb = 0; rb < ROWS; rb += 4) {
      float4 g;
      g.x = g.y = g.z = g.w = bh_r;
      #pragma unroll
      for (int k = 0; k < KH; k++) {
        float  wv = wreg[k];
        float4 hv = *reinterpret_cast<const float4*>(hbase + k * RPAD + rb);
        g.x = fmaf(wv, hv.x, g.x); g.y = fmaf(wv, hv.y, g.y);
        g.z = fmaf(wv, hv.z, g.z); g.w = fmaf(wv, hv.w, g.w);
      }
      *reinterpret_cast<float4*>(&sm.ghp[half][o][rb]) = g;
    }
    // ---- gi (half 0 only; tiny: 6 FMAs per row) ----
    if (!half) {
      #pragma unroll 1
      for (int rb = 0; rb < ROWS; rb += 4) {
        float4 g;
        g.x = g.y = g.z = g.w = bi_r;
        #pragma unroll
        for (int i = 0; i < II; i++) {
          float  wv = sm.wihs[o][i];
          float4 xv = *reinterpret_cast<const float4*>(&sm.x[i][rb]);
          g.x = fmaf(wv, xv.x, g.x); g.y = fmaf(wv, xv.y, g.y);
          g.z = fmaf(wv, xv.z, g.z); g.w = fmaf(wv, xv.w, g.w);
        }
        *reinterpret_cast<float4*>(&sm.gi[o][rb]) = g;
      }
    }
    __syncthreads();   // S2: gates ready

    // ---- gate combine ----
    for (int idx = tid; idx < HH * ROWS; idx += NT) {
      int j = idx >> 4, r = idx & (ROWS - 1);
      float gr = sm.gi[j][r]        + sm.ghp[0][j][r]        + sm.ghp[1][j][r];
      float gz = sm.gi[j +   HH][r] + sm.ghp[0][j +   HH][r] + sm.ghp[1][j +   HH][r];
      float hn =                      sm.ghp[0][j + 2*HH][r] + sm.ghp[1][j + 2*HH][r];
      float rg = sigf(gr);
      float zg = sigf(gz);
      float ng = tanhfast(fmaf(rg, hn, sm.gi[j + 2*HH][r]));
      float ho = sm.h[j][r];
      sm.h[j][r] = fmaf(zg, ho - ng, ng);
    }
    __syncthreads();   // S3: h' ready

    // ---- decoder head ----
    if (t >= TT) {
      const int j   = tid & (HH - 1);
      const int grp = tid >> 7;            // 0..5
      for (int r = grp; r < ROWS; r += 6) {
        float acc = sm.b1s[j];
        #pragma unroll 8
        for (int k = 0; k < HH; k++)
          acc = fmaf(sm.w1t[k][j], sm.h[k][r], acc);
        sm.a[r][j] = fmaxf(acc, 0.0f);
      }
      __syncthreads(); // S4: a ready

      if (tid < II * ROWS) {   // 96 threads
        int i = tid >> 4, r = tid & (ROWS - 1);
        float acc = sm.b2s[i];
        #pragma unroll 8
        for (int k = 0; k < HH; k++)
          acc = fmaf(sm.w2s[i][k], sm.a[r][k], acc);
        sm.x[i][r] = acc;
        out[(size_t)(row0 + r) * (FUTN * II) + (t - TT) * II + i] = acc;
      }
      // next-iteration S1 orders sm.x reuse
    }
  }
}

extern "C" void kernel_launch(void* const* d_in, const int* in_sizes, int n_in,
                              void* d_out, int out_size) {
  const float* history = (const float*)d_in[0];
  const float* w_ih    = (const float*)d_in[1];
  const float* w_hh    = (const float*)d_in[2];
  const float* b_ih    = (const float*)d_in[3];
  const float* b_hh    = (const float*)d_in[4];
  const float* w1      = (const float*)d_in[5];
  const float* b1      = (const float*)d_in[6];
  const float* w2      = (const float*)d_in[7];
  const float* b2      = (const float*)d_in[8];
  float* out = (float*)d_out;

  const int smem = (int)sizeof(Smem);   // ~190 KB
  cudaFuncSetAttribute(gru_traj_kernel,
                       cudaFuncAttributeMaxDynamicSharedMemorySize, smem);
  gru_traj_kernel<<<BSZ / ROWS, NT, smem>>>(
      history, w_ih, w_hh, b_ih, b_hh, w1, b1, w2, b2, out);
}

// round 4
// speedup vs baseline: 1.3817x; 1.0015x over previous
#include <cuda_runtime.h>

// TrajectoryGRU: B=16384, T=50, I=6, H=128, FUT=30
// Split-K persistent GRU: 768 threads/CTA. Thread (o, half) holds 64 of
// w_hh[o]'s 128 weights in registers, computes a partial gate sum for 16
// batch rows into SMEM; combine stage sums the halves. 24 warps/SM.

#define BSZ   16384
#define TT    50
#define II    6
#define HH    128
#define GG    384        // 3*H
#define FUTN  30
#define ROWS  16         // batch rows per CTA
#define RPAD  20         // 20*o mod 32 covers all banks for STS.128
#define NT    768
#define KH    64         // k-half length

struct Smem {
  float h  [HH][RPAD];          // hidden state [j][r]
  float gi [GG][RPAD];          // input-gate preacts (incl b_ih)
  float ghp[2][GG][RPAD];       // partial hidden-gate preacts (half0 incl b_hh)
  float x  [II][RPAD];          // current input
  float a  [ROWS][HH + 2];      // relu(h@w1^T+b1)
  float w1t[HH][HH];            // w1 transposed
  float w2s[II][HH + 2];
  float wihs[GG][II];
  float b1s[HH];
  float b2s[II];
};

__device__ __forceinline__ float sigf(float v) {
  return 1.0f / (1.0f + __expf(-v));
}
__device__ __forceinline__ float tanhfast(float v) {
  float av = fabsf(v);
  float e  = __expf(-2.0f * av);
  float t  = (1.0f - e) / (1.0f + e);
  return copysignf(t, v);
}

__global__ void __launch_bounds__(NT, 1)
gru_traj_kernel(const float* __restrict__ history,
                const float* __restrict__ w_ih,
                const float* __restrict__ w_hh,
                const float* __restrict__ b_ih,
                const float* __restrict__ b_hh,
                const float* __restrict__ w1,
                const float* __restrict__ b1,
                const float* __restrict__ w2,
                const float* __restrict__ b2,
                float* __restrict__ out)
{
  extern __shared__ char smem_raw[];
  Smem& sm = *reinterpret_cast<Smem*>(smem_raw);
  const int tid  = threadIdx.x;           // 0..767
  const int half = (tid >= GG) ? 1 : 0;
  const int o    = tid - half * GG;       // gate index 0..383
  const int row0 = blockIdx.x * ROWS;

  // ---- weight-stationary registers: half of w_hh row o (64 regs) ----
  float wreg[KH];
  {
    const float4* w4 =
        reinterpret_cast<const float4*>(w_hh + o * HH + half * KH);
    #pragma unroll
    for (int k4 = 0; k4 < KH / 4; k4++) {
      float4 v = w4[k4];
      wreg[4*k4+0] = v.x; wreg[4*k4+1] = v.y;
      wreg[4*k4+2] = v.z; wreg[4*k4+3] = v.w;
    }
  }
  const float bh_r = half ? 0.0f : b_hh[o];
  const float bi_r = b_ih[o];             // used by half 0 only

  // ---- shared weights ----
  for (int idx = tid; idx < HH * HH; idx += NT) {
    int j = idx >> 7, k = idx & (HH - 1);
    sm.w1t[k][j] = w1[idx];
  }
  for (int idx = tid; idx < II * HH; idx += NT)
    sm.w2s[idx >> 7][idx & (HH - 1)] = w2[idx];
  for (int idx = tid; idx < GG * II; idx += NT)
    sm.wihs[idx / II][idx % II] = w_ih[idx];
  if (tid < HH) sm.b1s[tid] = b1[tid];
  if (tid < II) sm.b2s[tid] = b2[tid];

  // ---- h = 0 ----
  for (int idx = tid; idx < HH * RPAD; idx += NT)
    (&sm.h[0][0])[idx] = 0.0f;

  for (int t = 0; t < TT + FUTN; t++) {
    if (t < TT) {
      if (tid < II * ROWS) {
        int r = tid / II, i = tid - r * II;
        sm.x[i][r] = history[(size_t)(row0 + r) * (TT * II) + t * II + i];
      }
    }
    __syncthreads();   // S1: x and h visible

    // ---- partial gh GEMM: ghp[half][o][:] ----
    const float* hbase = &sm.h[half * KH][0];
    #pragma unroll 1
    for (int rb = 0; rb < ROWS; rb += 4) {
      float4 g;
      g.x = g.y = g.z = g.w = bh_r;
      #pragma unroll
      for (int k = 0; k < KH; k++) {
        float  wv = wreg[k];
        float4 hv = *reinterpret_cast<const float4*>(hbase + k * RPAD + rb);
        g.x = fmaf(wv, hv.x, g.x); g.y = fmaf(wv, hv.y, g.y);
        g.z = fmaf(wv, hv.z, g.z); g.w = fmaf(wv, hv.w, g.w);
      }
      *reinterpret_cast<float4*>(&sm.ghp[half][o][rb]) = g;
    }
    // ---- gi (half 0 only; tiny: 6 FMAs per row) ----
    if (!half) {
      #pragma unroll 1
      for (int rb = 0; rb < ROWS; rb += 4) {
        float4 g;
        g.x = g.y = g.z = g.w = bi_r;
        #pragma unroll
        for (int i = 0; i < II; i++) {
          float  wv = sm.wihs[o][i];
          float4 xv = *reinterpret_cast<const float4*>(&sm.x[i][rb]);
          g.x = fmaf(wv, xv.x, g.x); g.y = fmaf(wv, xv.y, g.y);
          g.z = fmaf(wv, xv.z, g.z); g.w = fmaf(wv, xv.w, g.w);
        }
        *reinterpret_cast<float4*>(&sm.gi[o][rb]) = g;
      }
    }
    __syncthreads();   // S2: gates ready

    // ---- gate combine ----
    for (int idx = tid; idx < HH * ROWS; idx += NT) {
      int j = idx >> 4, r = idx & (ROWS - 1);
      float gr = sm.gi[j][r]        + sm.ghp[0][j][r]        + sm.ghp[1][j][r];
      float gz = sm.gi[j +   HH][r] + sm.ghp[0][j +   HH][r] + sm.ghp[1][j +   HH][r];
      float hn =                      sm.ghp[0][j + 2*HH][r] + sm.ghp[1][j + 2*HH][r];
      float rg = sigf(gr);
      float zg = sigf(gz);
      float ng = tanhfast(fmaf(rg, hn, sm.gi[j + 2*HH][r]));
      float ho = sm.h[j][r];
      sm.h[j][r] = fmaf(zg, ho - ng, ng);
    }
    __syncthreads();   // S3: h' ready

    // ---- decoder head ----
    if (t >= TT) {
      const int j   = tid & (HH - 1);
      const int grp = tid >> 7;            // 0..5
      for (int r = grp; r < ROWS; r += 6) {
        float acc = sm.b1s[j];
        #pragma unroll 8
        for (int k = 0; k < HH; k++)
          acc = fmaf(sm.w1t[k][j], sm.h[k][r], acc);
        sm.a[r][j] = fmaxf(acc, 0.0f);
      }
      __syncthreads(); // S4: a ready

      if (tid < II * ROWS) {   // 96 threads
        int i = tid >> 4, r = tid & (ROWS - 1);
        float acc = sm.b2s[i];
        #pragma unroll 8
        for (int k = 0; k < HH; k++)
          acc = fmaf(sm.w2s[i][k], sm.a[r][k], acc);
        sm.x[i][r] = acc;
        out[(size_t)(row0 + r) * (FUTN * II) + (t - TT) * II + i] = acc;
      }
      // next-iteration S1 orders sm.x reuse
    }
  }
}

extern "C" void kernel_launch(void* const* d_in, const int* in_sizes, int n_in,
                              void* d_out, int out_size) {
  const float* history = (const float*)d_in[0];
  const float* w_ih    = (const float*)d_in[1];
  const float* w_hh    = (const float*)d_in[2];
  const float* b_ih    = (const float*)d_in[3];
  const float* b_hh    = (const float*)d_in[4];
  const float* w1      = (const float*)d_in[5];
  const float* b1      = (const float*)d_in[6];
  const float* w2      = (const float*)d_in[7];
  const float* b2      = (const float*)d_in[8];
  float* out = (float*)d_out;

  const int smem = (int)sizeof(Smem);   // ~190 KB
  cudaFuncSetAttribute(gru_traj_kernel,
                       cudaFuncAttributeMaxDynamicSharedMemorySize, smem);
  gru_traj_kernel<<<BSZ / ROWS, NT, smem>>>(
      history, w_ih, w_hh, b_ih, b_hh, w1, b1, w2, b2, out);
}

// round 7
// speedup vs baseline: 5.3434x; 3.8671x over previous
#include <cuda_runtime.h>
#include <cuda_bf16.h>
#include <cstdint>

// TrajectoryGRU via mma.sync (HMMA bf16, baseline PTX): B=16384, T=50, I=6,
// H=128, FUT=30. 8 warps/CTA, 32 batch rows/CTA, grid 512.
// Warp w owns m16-tiles {g*128 + w*16 : g=0,1,2} of W_hh -> r,z,n fragments
// for the same (j,n) live in the same lane: register-resident gate combine.
// bf16x3 passes (w0h0 + w0h1 + w1h0) with fp32 accumulators.

#define TT   50
#define II   6
#define HH   128
#define FUTN 30
#define ROWS 32
#define NT   256

// smem byte offsets (from 16B-aligned dynamic smem base)
#define OFF_WLO  0        // W_hh lo frags  [w8][mt3][kc8][lane32] uint4 = 98304
#define OFF_W1F  98304    // head w1 frags  [hl2][w8][kc8][lane32] uint4 = 65536
#define OFF_HF   163840   // h B-frags [buf2][kc8][nt4][lane32][reg2] u32 = 16384
#define OFF_AT   180224   // head act [128][34] f32 = 17408
#define OFF_XS   197632   // x [32][6] f32 = 768
#define OFF_WIH  198400   // w_ih [384][6] f32 = 9216
#define OFF_W2S  207616   // w2 [6][128] f32 = 3072
#define OFF_B1S  210688   // b1 [128] f32 = 512
#define OFF_B2S  211200   // b2 [6] f32 (pad 32)
#define SMEM_TOTAL 211232

__device__ __forceinline__ void mma16816(float* d, const uint32_t* a,
                                         uint32_t b0, uint32_t b1) {
  asm volatile(
    "mma.sync.aligned.m16n8k16.row.col.f32.bf16.bf16.f32 "
    "{%0,%1,%2,%3}, {%4,%5,%6,%7}, {%8,%9}, {%0,%1,%2,%3};"
    : "+f"(d[0]), "+f"(d[1]), "+f"(d[2]), "+f"(d[3])
    : "r"(a[0]), "r"(a[1]), "r"(a[2]), "r"(a[3]), "r"(b0), "r"(b1));
}
__device__ __forceinline__ uint32_t packhi(float2 v) {
  __nv_bfloat162 p(__float2bfloat16(v.x), __float2bfloat16(v.y));
  return *reinterpret_cast<uint32_t*>(&p);
}
__device__ __forceinline__ uint32_t packlo(float2 v) {
  float rx = v.x - __bfloat162float(__float2bfloat16(v.x));
  float ry = v.y - __bfloat162float(__float2bfloat16(v.y));
  __nv_bfloat162 p(__float2bfloat16(rx), __float2bfloat16(ry));
  return *reinterpret_cast<uint32_t*>(&p);
}
__device__ __forceinline__ float sigf(float v) {
  return __fdividef(1.0f, 1.0f + __expf(-v));
}
__device__ __forceinline__ float tanhfast(float v) {
  float av = fabsf(v);
  float e  = __expf(-2.0f * av);
  return copysignf(__fdividef(1.0f - e, 1.0f + e), v);
}

__global__ void __launch_bounds__(NT, 1)
gru_mma_kernel(const float* __restrict__ history,
               const float* __restrict__ w_ih,
               const float* __restrict__ w_hh,
               const float* __restrict__ b_ih,
               const float* __restrict__ b_hh,
               const float* __restrict__ w1,
               const float* __restrict__ b1,
               const float* __restrict__ w2,
               const float* __restrict__ b2,
               float* __restrict__ out)
{
  extern __shared__ char sb[];
  const int tid = threadIdx.x;
  const int w   = tid >> 5;        // warp 0..7
  const int l   = tid & 31;
  const int grp = l >> 2;          // 0..7 (m-row within tile)
  const int tg  = l & 3;           // 0..3 (n/k selector)
  const int row0 = blockIdx.x * ROWS;

  const int jA = w * 16 + grp;     // hidden index (row-half A)
  const int jB = jA + 8;           // row-half B

  float* xs   = (float*)(sb + OFF_XS);
  float* wih  = (float*)(sb + OFF_WIH);
  float* w2s  = (float*)(sb + OFF_W2S);
  float* b1s  = (float*)(sb + OFF_B1S);
  float* b2s  = (float*)(sb + OFF_B2S);

  // ---------- init: shared weight copies ----------
  for (int idx = tid; idx < 384 * II; idx += NT) wih[idx] = w_ih[idx];
  for (int idx = tid; idx < II * HH; idx += NT)  w2s[idx] = w2[idx];
  if (tid < HH) b1s[tid] = b1[tid];
  if (tid < II) b2s[tid] = b2[tid];
  // zero h fragments (h0 = 0)
  for (int idx = tid; idx < 4096; idx += NT)
    ((uint32_t*)(sb + OFF_HF))[idx] = 0u;

  // ---------- W_hh fragments: hi in regs, lo in smem ----------
  uint32_t ahi[3][8][4];
  #pragma unroll
  for (int mt = 0; mt < 3; mt++) {
    #pragma unroll
    for (int kc = 0; kc < 8; kc++) {
      int rA = mt * HH + w * 16 + grp;
      int rB = rA + 8;
      int k0 = kc * 16 + tg * 2;
      float2 vA0 = *(const float2*)(w_hh + (size_t)rA * HH + k0);
      float2 vB0 = *(const float2*)(w_hh + (size_t)rB * HH + k0);
      float2 vA1 = *(const float2*)(w_hh + (size_t)rA * HH + k0 + 8);
      float2 vB1 = *(const float2*)(w_hh + (size_t)rB * HH + k0 + 8);
      ahi[mt][kc][0] = packhi(vA0); ahi[mt][kc][1] = packhi(vB0);
      ahi[mt][kc][2] = packhi(vA1); ahi[mt][kc][3] = packhi(vB1);
      uint4 lo = { packlo(vA0), packlo(vB0), packlo(vA1), packlo(vB1) };
      *(uint4*)(sb + OFF_WLO + ((((w * 3 + mt) * 8) + kc) * 32 + l) * 16) = lo;
    }
  }
  // ---------- head w1 fragments (hi+lo) into smem ----------
  #pragma unroll
  for (int kc = 0; kc < 8; kc++) {
    int rA = w * 16 + grp, rB = rA + 8;
    int k0 = kc * 16 + tg * 2;
    float2 vA0 = *(const float2*)(w1 + (size_t)rA * HH + k0);
    float2 vB0 = *(const float2*)(w1 + (size_t)rB * HH + k0);
    float2 vA1 = *(const float2*)(w1 + (size_t)rA * HH + k0 + 8);
    float2 vB1 = *(const float2*)(w1 + (size_t)rB * HH + k0 + 8);
    uint4 hi = { packhi(vA0), packhi(vB0), packhi(vA1), packhi(vB1) };
    uint4 lo = { packlo(vA0), packlo(vB0), packlo(vA1), packlo(vB1) };
    *(uint4*)(sb + OFF_W1F + (((0 * 8 + w) * 8 + kc) * 32 + l) * 16) = hi;
    *(uint4*)(sb + OFF_W1F + (((1 * 8 + w) * 8 + kc) * 32 + l) * 16) = lo;
  }

  // ---------- per-thread biases ----------
  const float brA  = b_ih[jA] + b_hh[jA];
  const float brB  = b_ih[jB] + b_hh[jB];
  const float bzA  = b_ih[HH + jA] + b_hh[HH + jA];
  const float bzB  = b_ih[HH + jB] + b_hh[HH + jB];
  const float binA = b_ih[2 * HH + jA];
  const float binB = b_ih[2 * HH + jB];
  const float bhnA = b_hh[2 * HH + jA];
  const float bhnB = b_hh[2 * HH + jB];

  float hreg[4][4];
  #pragma unroll
  for (int a = 0; a < 4; a++)
    #pragma unroll
    for (int b = 0; b < 4; b++) hreg[a][b] = 0.0f;

  // HF producer byte offset (j-dependent part): lane-slot + reg + half
  // slot = (w*4+nt)*32 + (tg*2+c)*4 + (grp>>1); u32 = slot*2 + rh; +2B if grp odd
  const uint32_t hfj = (uint32_t)((grp >> 1) * 8) + (uint32_t)((grp & 1) * 2);

  for (int t = 0; t < TT + FUTN; t++) {
    if (t < TT && tid < ROWS * II) {
      int n = tid / II, i = tid - n * II;
      xs[tid] = history[(size_t)(row0 + n) * (TT * II) + t * II + i];
    }
    __syncthreads();   // xs + HF(h_{t-1}) visible

    // ---- D init: gi on CUDA cores (r,z incl. both biases; n split) ----
    float dR[4][4], dZ[4][4], dN[4][4], gin[4][4];
    #pragma unroll
    for (int nt = 0; nt < 4; nt++)
      #pragma unroll
      for (int c = 0; c < 2; c++) {
        dR[nt][c] = brA;  dR[nt][2 + c] = brB;
        dZ[nt][c] = bzA;  dZ[nt][2 + c] = bzB;
        dN[nt][c] = bhnA; dN[nt][2 + c] = bhnB;
        gin[nt][c] = binA; gin[nt][2 + c] = binB;
      }
    #pragma unroll
    for (int i = 0; i < II; i++) {
      float wrA = wih[jA * II + i],            wrB = wih[jB * II + i];
      float wzA = wih[(HH + jA) * II + i],     wzB = wih[(HH + jB) * II + i];
      float wnA = wih[(2 * HH + jA) * II + i], wnB = wih[(2 * HH + jB) * II + i];
      #pragma unroll
      for (int nt = 0; nt < 4; nt++)
        #pragma unroll
        for (int c = 0; c < 2; c++) {
          float xv = xs[(nt * 8 + tg * 2 + c) * II + i];
          dR[nt][c]      = fmaf(wrA, xv, dR[nt][c]);
          dR[nt][2 + c]  = fmaf(wrB, xv, dR[nt][2 + c]);
          dZ[nt][c]      = fmaf(wzA, xv, dZ[nt][c]);
          dZ[nt][2 + c]  = fmaf(wzB, xv, dZ[nt][2 + c]);
          gin[nt][c]     = fmaf(wnA, xv, gin[nt][c]);
          gin[nt][2 + c] = fmaf(wnB, xv, gin[nt][2 + c]);
        }
    }

    // ---- gh mma chain: 3 gates x 4 ntiles x 8 kchunks x 3 passes ----
    #pragma unroll
    for (int kc = 0; kc < 8; kc++) {
      uint2 b0f[4], b1f[4];
      #pragma unroll
      for (int nt = 0; nt < 4; nt++) {
        b0f[nt] = *(const uint2*)(sb + OFF_HF + (((kc * 4 + nt) * 32 + l) * 8));
        b1f[nt] = *(const uint2*)(sb + OFF_HF + 8192 + (((kc * 4 + nt) * 32 + l) * 8));
      }
      #define GH_MT(mt, Dg) { \
        uint4 lov = *(const uint4*)(sb + OFF_WLO + \
                     ((((w * 3 + (mt)) * 8) + kc) * 32 + l) * 16); \
        uint32_t alo[4] = { lov.x, lov.y, lov.z, lov.w }; \
        _Pragma("unroll") \
        for (int nt = 0; nt < 4; nt++) { \
          mma16816(Dg[nt], ahi[mt][kc], b0f[nt].x, b0f[nt].y); \
          mma16816(Dg[nt], ahi[mt][kc], b1f[nt].x, b1f[nt].y); \
          mma16816(Dg[nt], alo,          b0f[nt].x, b0f[nt].y); \
        } }
      GH_MT(0, dR)
      GH_MT(1, dZ)
      GH_MT(2, dN)
      #undef GH_MT
    }
    __syncthreads();   // all HF reads done before combine overwrites

    // ---- register-resident gate combine + h update + HF write ----
    #pragma unroll
    for (int nt = 0; nt < 4; nt++)
      #pragma unroll
      for (int rh = 0; rh < 2; rh++)
        #pragma unroll
        for (int c = 0; c < 2; c++) {
          int e = rh * 2 + c;
          float rg = sigf(dR[nt][e]);
          float zg = sigf(dZ[nt][e]);
          float ng = tanhfast(fmaf(rg, dN[nt][e], gin[nt][e]));
          float h  = fmaf(zg, hreg[nt][e] - ng, ng);
          hreg[nt][e] = h;
          __nv_bfloat16 hi = __float2bfloat16(h);
          __nv_bfloat16 lo = __float2bfloat16(h - __bfloat162float(hi));
          uint32_t off = (uint32_t)(((w * 4 + nt) * 32 + (tg * 2 + c) * 4) * 8)
                       + (uint32_t)(rh * 4) + hfj;
          *(__nv_bfloat16*)(sb + OFF_HF + off) = hi;
          *(__nv_bfloat16*)(sb + OFF_HF + 8192 + off) = lo;
        }

    // ---- decoder head ----
    if (t >= TT) {
      __syncthreads();  // HF(h_t) complete for head mma
      float hd[4][4];
      #pragma unroll
      for (int nt = 0; nt < 4; nt++)
        #pragma unroll
        for (int e = 0; e < 4; e++) hd[nt][e] = 0.0f;
      #pragma unroll
      for (int kc = 0; kc < 8; kc++) {
        uint2 b0f[4], b1f[4];
        #pragma unroll
        for (int nt = 0; nt < 4; nt++) {
          b0f[nt] = *(const uint2*)(sb + OFF_HF + (((kc * 4 + nt) * 32 + l) * 8));
          b1f[nt] = *(const uint2*)(sb + OFF_HF + 8192 + (((kc * 4 + nt) * 32 + l) * 8));
        }
        uint4 hv = *(const uint4*)(sb + OFF_W1F + (((0 * 8 + w) * 8 + kc) * 32 + l) * 16);
        uint4 lv = *(const uint4*)(sb + OFF_W1F + (((1 * 8 + w) * 8 + kc) * 32 + l) * 16);
        uint32_t ah[4] = { hv.x, hv.y, hv.z, hv.w };
        uint32_t al[4] = { lv.x, lv.y, lv.z, lv.w };
        #pragma unroll
        for (int nt = 0; nt < 4; nt++) {
          mma16816(hd[nt], ah, b0f[nt].x, b0f[nt].y);
          mma16816(hd[nt], ah, b1f[nt].x, b1f[nt].y);
          mma16816(hd[nt], al, b0f[nt].x, b0f[nt].y);
        }
      }
      float b1A = b1s[jA], b1B = b1s[jB];
      #pragma unroll
      for (int nt = 0; nt < 4; nt++) {
        float2 vA = { fmaxf(hd[nt][0] + b1A, 0.0f), fmaxf(hd[nt][1] + b1A, 0.0f) };
        float2 vB = { fmaxf(hd[nt][2] + b1B, 0.0f), fmaxf(hd[nt][3] + b1B, 0.0f) };
        *(float2*)(sb + OFF_AT + ((size_t)jA * 34 + nt * 8 + tg * 2) * 4) = vA;
        *(float2*)(sb + OFF_AT + ((size_t)jB * 34 + nt * 8 + tg * 2) * 4) = vB;
      }
      __syncthreads();  // AT ready
      if (tid < ROWS * II) {
        int n = tid / II, i = tid - n * II;
        const float* at  = (const float*)(sb + OFF_AT);
        const float* w2p = w2s + i * HH;
        float acc = b2s[i];
        #pragma unroll 8
        for (int k = 0; k < HH; k++)
          acc = fmaf(at[k * 34 + n], w2p[k], acc);
        xs[tid] = acc;   // feeds next step's gi (ordered by loop-top sync)
        out[(size_t)(row0 + n) * (FUTN * II) + (size_t)(t - TT) * II + i] = acc;
      }
    }
  }
}

extern "C" void kernel_launch(void* const* d_in, const int* in_sizes, int n_in,
                              void* d_out, int out_size) {
  const float* history = (const float*)d_in[0];
  const float* w_ih    = (const float*)d_in[1];
  const float* w_hh    = (const float*)d_in[2];
  const float* b_ih    = (const float*)d_in[3];
  const float* b_hh    = (const float*)d_in[4];
  const float* w1      = (const float*)d_in[5];
  const float* b1      = (const float*)d_in[6];
  const float* w2      = (const float*)d_in[7];
  const float* b2      = (const float*)d_in[8];
  float* out = (float*)d_out;

  cudaFuncSetAttribute(gru_mma_kernel,
                       cudaFuncAttributeMaxDynamicSharedMemorySize, SMEM_TOTAL);
  gru_mma_kernel<<<16384 / ROWS, NT, SMEM_TOTAL>>>(
      history, w_ih, w_hh, b_ih, b_hh, w1, b1, w2, b2, out);
}

// round 8
// speedup vs baseline: 5.3475x; 1.0008x over previous
#include <cuda_runtime.h>
#include <cuda_bf16.h>
#include <cstdint>

// TrajectoryGRU via mma.sync (HMMA bf16, baseline PTX): B=16384, T=50, I=6,
// H=128, FUT=30. 8 warps/CTA, 32 batch rows/CTA, grid 512.
// Warp w owns m16-tiles {g*128 + w*16 : g=0,1,2} of W_hh -> r,z,n fragments
// for the same (j,n) live in the same lane: register-resident gate combine.
// bf16x3 passes (w0h0 + w0h1 + w1h0) with fp32 accumulators.

#define TT   50
#define II   6
#define HH   128
#define FUTN 30
#define ROWS 32
#define NT   256

// smem byte offsets (from 16B-aligned dynamic smem base)
#define OFF_WLO  0        // W_hh lo frags  [w8][mt3][kc8][lane32] uint4 = 98304
#define OFF_W1F  98304    // head w1 frags  [hl2][w8][kc8][lane32] uint4 = 65536
#define OFF_HF   163840   // h B-frags [buf2][kc8][nt4][lane32][reg2] u32 = 16384
#define OFF_AT   180224   // head act [128][34] f32 = 17408
#define OFF_XS   197632   // x [32][6] f32 = 768
#define OFF_WIH  198400   // w_ih [384][6] f32 = 9216
#define OFF_W2S  207616   // w2 [6][128] f32 = 3072
#define OFF_B1S  210688   // b1 [128] f32 = 512
#define OFF_B2S  211200   // b2 [6] f32 (pad 32)
#define SMEM_TOTAL 211232

__device__ __forceinline__ void mma16816(float* d, const uint32_t* a,
                                         uint32_t b0, uint32_t b1) {
  asm volatile(
    "mma.sync.aligned.m16n8k16.row.col.f32.bf16.bf16.f32 "
    "{%0,%1,%2,%3}, {%4,%5,%6,%7}, {%8,%9}, {%0,%1,%2,%3};"
    : "+f"(d[0]), "+f"(d[1]), "+f"(d[2]), "+f"(d[3])
    : "r"(a[0]), "r"(a[1]), "r"(a[2]), "r"(a[3]), "r"(b0), "r"(b1));
}
__device__ __forceinline__ uint32_t packhi(float2 v) {
  __nv_bfloat162 p(__float2bfloat16(v.x), __float2bfloat16(v.y));
  return *reinterpret_cast<uint32_t*>(&p);
}
__device__ __forceinline__ uint32_t packlo(float2 v) {
  float rx = v.x - __bfloat162float(__float2bfloat16(v.x));
  float ry = v.y - __bfloat162float(__float2bfloat16(v.y));
  __nv_bfloat162 p(__float2bfloat16(rx), __float2bfloat16(ry));
  return *reinterpret_cast<uint32_t*>(&p);
}
__device__ __forceinline__ float sigf(float v) {
  return __fdividef(1.0f, 1.0f + __expf(-v));
}
__device__ __forceinline__ float tanhfast(float v) {
  float av = fabsf(v);
  float e  = __expf(-2.0f * av);
  return copysignf(__fdividef(1.0f - e, 1.0f + e), v);
}

__global__ void __launch_bounds__(NT, 1)
gru_mma_kernel(const float* __restrict__ history,
               const float* __restrict__ w_ih,
               const float* __restrict__ w_hh,
               const float* __restrict__ b_ih,
               const float* __restrict__ b_hh,
               const float* __restrict__ w1,
               const float* __restrict__ b1,
               const float* __restrict__ w2,
               const float* __restrict__ b2,
               float* __restrict__ out)
{
  extern __shared__ char sb[];
  const int tid = threadIdx.x;
  const int w   = tid >> 5;        // warp 0..7
  const int l   = tid & 31;
  const int grp = l >> 2;          // 0..7 (m-row within tile)
  const int tg  = l & 3;           // 0..3 (n/k selector)
  const int row0 = blockIdx.x * ROWS;

  const int jA = w * 16 + grp;     // hidden index (row-half A)
  const int jB = jA + 8;           // row-half B

  float* xs   = (float*)(sb + OFF_XS);
  float* wih  = (float*)(sb + OFF_WIH);
  float* w2s  = (float*)(sb + OFF_W2S);
  float* b1s  = (float*)(sb + OFF_B1S);
  float* b2s  = (float*)(sb + OFF_B2S);

  // ---------- init: shared weight copies ----------
  for (int idx = tid; idx < 384 * II; idx += NT) wih[idx] = w_ih[idx];
  for (int idx = tid; idx < II * HH; idx += NT)  w2s[idx] = w2[idx];
  if (tid < HH) b1s[tid] = b1[tid];
  if (tid < II) b2s[tid] = b2[tid];
  // zero h fragments (h0 = 0)
  for (int idx = tid; idx < 4096; idx += NT)
    ((uint32_t*)(sb + OFF_HF))[idx] = 0u;

  // ---------- W_hh fragments: hi in regs, lo in smem ----------
  uint32_t ahi[3][8][4];
  #pragma unroll
  for (int mt = 0; mt < 3; mt++) {
    #pragma unroll
    for (int kc = 0; kc < 8; kc++) {
      int rA = mt * HH + w * 16 + grp;
      int rB = rA + 8;
      int k0 = kc * 16 + tg * 2;
      float2 vA0 = *(const float2*)(w_hh + (size_t)rA * HH + k0);
      float2 vB0 = *(const float2*)(w_hh + (size_t)rB * HH + k0);
      float2 vA1 = *(const float2*)(w_hh + (size_t)rA * HH + k0 + 8);
      float2 vB1 = *(const float2*)(w_hh + (size_t)rB * HH + k0 + 8);
      ahi[mt][kc][0] = packhi(vA0); ahi[mt][kc][1] = packhi(vB0);
      ahi[mt][kc][2] = packhi(vA1); ahi[mt][kc][3] = packhi(vB1);
      uint4 lo = { packlo(vA0), packlo(vB0), packlo(vA1), packlo(vB1) };
      *(uint4*)(sb + OFF_WLO + ((((w * 3 + mt) * 8) + kc) * 32 + l) * 16) = lo;
    }
  }
  // ---------- head w1 fragments (hi+lo) into smem ----------
  #pragma unroll
  for (int kc = 0; kc < 8; kc++) {
    int rA = w * 16 + grp, rB = rA + 8;
    int k0 = kc * 16 + tg * 2;
    float2 vA0 = *(const float2*)(w1 + (size_t)rA * HH + k0);
    float2 vB0 = *(const float2*)(w1 + (size_t)rB * HH + k0);
    float2 vA1 = *(const float2*)(w1 + (size_t)rA * HH + k0 + 8);
    float2 vB1 = *(const float2*)(w1 + (size_t)rB * HH + k0 + 8);
    uint4 hi = { packhi(vA0), packhi(vB0), packhi(vA1), packhi(vB1) };
    uint4 lo = { packlo(vA0), packlo(vB0), packlo(vA1), packlo(vB1) };
    *(uint4*)(sb + OFF_W1F + (((0 * 8 + w) * 8 + kc) * 32 + l) * 16) = hi;
    *(uint4*)(sb + OFF_W1F + (((1 * 8 + w) * 8 + kc) * 32 + l) * 16) = lo;
  }

  // ---------- per-thread biases ----------
  const float brA  = b_ih[jA] + b_hh[jA];
  const float brB  = b_ih[jB] + b_hh[jB];
  const float bzA  = b_ih[HH + jA] + b_hh[HH + jA];
  const float bzB  = b_ih[HH + jB] + b_hh[HH + jB];
  const float binA = b_ih[2 * HH + jA];
  const float binB = b_ih[2 * HH + jB];
  const float bhnA = b_hh[2 * HH + jA];
  const float bhnB = b_hh[2 * HH + jB];

  float hreg[4][4];
  #pragma unroll
  for (int a = 0; a < 4; a++)
    #pragma unroll
    for (int b = 0; b < 4; b++) hreg[a][b] = 0.0f;

  // HF producer byte offset (j-dependent part): lane-slot + reg + half
  // slot = (w*4+nt)*32 + (tg*2+c)*4 + (grp>>1); u32 = slot*2 + rh; +2B if grp odd
  const uint32_t hfj = (uint32_t)((grp >> 1) * 8) + (uint32_t)((grp & 1) * 2);

  for (int t = 0; t < TT + FUTN; t++) {
    if (t < TT && tid < ROWS * II) {
      int n = tid / II, i = tid - n * II;
      xs[tid] = history[(size_t)(row0 + n) * (TT * II) + t * II + i];
    }
    __syncthreads();   // xs + HF(h_{t-1}) visible

    // ---- D init: gi on CUDA cores (r,z incl. both biases; n split) ----
    float dR[4][4], dZ[4][4], dN[4][4], gin[4][4];
    #pragma unroll
    for (int nt = 0; nt < 4; nt++)
      #pragma unroll
      for (int c = 0; c < 2; c++) {
        dR[nt][c] = brA;  dR[nt][2 + c] = brB;
        dZ[nt][c] = bzA;  dZ[nt][2 + c] = bzB;
        dN[nt][c] = bhnA; dN[nt][2 + c] = bhnB;
        gin[nt][c] = binA; gin[nt][2 + c] = binB;
      }
    #pragma unroll
    for (int i = 0; i < II; i++) {
      float wrA = wih[jA * II + i],            wrB = wih[jB * II + i];
      float wzA = wih[(HH + jA) * II + i],     wzB = wih[(HH + jB) * II + i];
      float wnA = wih[(2 * HH + jA) * II + i], wnB = wih[(2 * HH + jB) * II + i];
      #pragma unroll
      for (int nt = 0; nt < 4; nt++)
        #pragma unroll
        for (int c = 0; c < 2; c++) {
          float xv = xs[(nt * 8 + tg * 2 + c) * II + i];
          dR[nt][c]      = fmaf(wrA, xv, dR[nt][c]);
          dR[nt][2 + c]  = fmaf(wrB, xv, dR[nt][2 + c]);
          dZ[nt][c]      = fmaf(wzA, xv, dZ[nt][c]);
          dZ[nt][2 + c]  = fmaf(wzB, xv, dZ[nt][2 + c]);
          gin[nt][c]     = fmaf(wnA, xv, gin[nt][c]);
          gin[nt][2 + c] = fmaf(wnB, xv, gin[nt][2 + c]);
        }
    }

    // ---- gh mma chain: 3 gates x 4 ntiles x 8 kchunks x 3 passes ----
    #pragma unroll
    for (int kc = 0; kc < 8; kc++) {
      uint2 b0f[4], b1f[4];
      #pragma unroll
      for (int nt = 0; nt < 4; nt++) {
        b0f[nt] = *(const uint2*)(sb + OFF_HF + (((kc * 4 + nt) * 32 + l) * 8));
        b1f[nt] = *(const uint2*)(sb + OFF_HF + 8192 + (((kc * 4 + nt) * 32 + l) * 8));
      }
      #define GH_MT(mt, Dg) { \
        uint4 lov = *(const uint4*)(sb + OFF_WLO + \
                     ((((w * 3 + (mt)) * 8) + kc) * 32 + l) * 16); \
        uint32_t alo[4] = { lov.x, lov.y, lov.z, lov.w }; \
        _Pragma("unroll") \
        for (int nt = 0; nt < 4; nt++) { \
          mma16816(Dg[nt], ahi[mt][kc], b0f[nt].x, b0f[nt].y); \
          mma16816(Dg[nt], ahi[mt][kc], b1f[nt].x, b1f[nt].y); \
          mma16816(Dg[nt], alo,          b0f[nt].x, b0f[nt].y); \
        } }
      GH_MT(0, dR)
      GH_MT(1, dZ)
      GH_MT(2, dN)
      #undef GH_MT
    }
    __syncthreads();   // all HF reads done before combine overwrites

    // ---- register-resident gate combine + h update + HF write ----
    #pragma unroll
    for (int nt = 0; nt < 4; nt++)
      #pragma unroll
      for (int rh = 0; rh < 2; rh++)
        #pragma unroll
        for (int c = 0; c < 2; c++) {
          int e = rh * 2 + c;
          float rg = sigf(dR[nt][e]);
          float zg = sigf(dZ[nt][e]);
          float ng = tanhfast(fmaf(rg, dN[nt][e], gin[nt][e]));
          float h  = fmaf(zg, hreg[nt][e] - ng, ng);
          hreg[nt][e] = h;
          __nv_bfloat16 hi = __float2bfloat16(h);
          __nv_bfloat16 lo = __float2bfloat16(h - __bfloat162float(hi));
          uint32_t off = (uint32_t)(((w * 4 + nt) * 32 + (tg * 2 + c) * 4) * 8)
                       + (uint32_t)(rh * 4) + hfj;
          *(__nv_bfloat16*)(sb + OFF_HF + off) = hi;
          *(__nv_bfloat16*)(sb + OFF_HF + 8192 + off) = lo;
        }

    // ---- decoder head ----
    if (t >= TT) {
      __syncthreads();  // HF(h_t) complete for head mma
      float hd[4][4];
      #pragma unroll
      for (int nt = 0; nt < 4; nt++)
        #pragma unroll
        for (int e = 0; e < 4; e++) hd[nt][e] = 0.0f;
      #pragma unroll
      for (int kc = 0; kc < 8; kc++) {
        uint2 b0f[4], b1f[4];
        #pragma unroll
        for (int nt = 0; nt < 4; nt++) {
          b0f[nt] = *(const uint2*)(sb + OFF_HF + (((kc * 4 + nt) * 32 + l) * 8));
          b1f[nt] = *(const uint2*)(sb + OFF_HF + 8192 + (((kc * 4 + nt) * 32 + l) * 8));
        }
        uint4 hv = *(const uint4*)(sb + OFF_W1F + (((0 * 8 + w) * 8 + kc) * 32 + l) * 16);
        uint4 lv = *(const uint4*)(sb + OFF_W1F + (((1 * 8 + w) * 8 + kc) * 32 + l) * 16);
        uint32_t ah[4] = { hv.x, hv.y, hv.z, hv.w };
        uint32_t al[4] = { lv.x, lv.y, lv.z, lv.w };
        #pragma unroll
        for (int nt = 0; nt < 4; nt++) {
          mma16816(hd[nt], ah, b0f[nt].x, b0f[nt].y);
          mma16816(hd[nt], ah, b1f[nt].x, b1f[nt].y);
          mma16816(hd[nt], al, b0f[nt].x, b0f[nt].y);
        }
      }
      float b1A = b1s[jA], b1B = b1s[jB];
      #pragma unroll
      for (int nt = 0; nt < 4; nt++) {
        float2 vA = { fmaxf(hd[nt][0] + b1A, 0.0f), fmaxf(hd[nt][1] + b1A, 0.0f) };
        float2 vB = { fmaxf(hd[nt][2] + b1B, 0.0f), fmaxf(hd[nt][3] + b1B, 0.0f) };
        *(float2*)(sb + OFF_AT + ((size_t)jA * 34 + nt * 8 + tg * 2) * 4) = vA;
        *(float2*)(sb + OFF_AT + ((size_t)jB * 34 + nt * 8 + tg * 2) * 4) = vB;
      }
      __syncthreads();  // AT ready
      if (tid < ROWS * II) {
        int n = tid / II, i = tid - n * II;
        const float* at  = (const float*)(sb + OFF_AT);
        const float* w2p = w2s + i * HH;
        float acc = b2s[i];
        #pragma unroll 8
        for (int k = 0; k < HH; k++)
          acc = fmaf(at[k * 34 + n], w2p[k], acc);
        xs[tid] = acc;   // feeds next step's gi (ordered by loop-top sync)
        out[(size_t)(row0 + n) * (FUTN * II) + (size_t)(t - TT) * II + i] = acc;
      }
    }
  }
}

extern "C" void kernel_launch(void* const* d_in, const int* in_sizes, int n_in,
                              void* d_out, int out_size) {
  const float* history = (const float*)d_in[0];
  const float* w_ih    = (const float*)d_in[1];
  const float* w_hh    = (const float*)d_in[2];
  const float* b_ih    = (const float*)d_in[3];
  const float* b_hh    = (const float*)d_in[4];
  const float* w1      = (const float*)d_in[5];
  const float* b1      = (const float*)d_in[6];
  const float* w2      = (const float*)d_in[7];
  const float* b2      = (const float*)d_in[8];
  float* out = (float*)d_out;

  cudaFuncSetAttribute(gru_mma_kernel,
                       cudaFuncAttributeMaxDynamicSharedMemorySize, SMEM_TOTAL);
  gru_mma_kernel<<<16384 / ROWS, NT, SMEM_TOTAL>>>(
      history, w_ih, w_hh, b_ih, b_hh, w1, b1, w2, b2, out);
}

// round 9
// speedup vs baseline: 5.3781x; 1.0057x over previous
#include <cuda_runtime.h>
#include <cuda_bf16.h>
#include <cstdint>

// TrajectoryGRU, mma.sync bf16, sub-tile software pipeline.
// 8 warps/CTA, 32 rows/CTA as two 16-row sub-tiles, grid 512.
// Bracket k (s=k&1): GH-mma(s, k>>1) fused with combine(1-s, (k-1)>>1).

#define TT    50
#define II    6
#define HH    128
#define FUTN  30
#define NSTEP (TT + FUTN)
#define NT    256

#define OFF_WLO  0        // W_hh lo frags [w8][g3][kc8][lane32] u4 = 98304
#define OFF_W1F  98304    // w1 frags hi/lo [hl2][w8][kc8][lane32] u4 = 65536
#define OFF_HF   163840   // [s2][hi4096|lo4096] = 16384
#define OFF_AT   180224   // [s2][128][18] f32 = 18432
#define OFF_XS   198656   // [s2][par2][96] f32 = 1536
#define OFF_WIH  200192   // [384][6] f32 = 9216
#define OFF_W2S  209408   // [6][128] f32 = 3072
#define OFF_B2S  212480   // [6] f32 + pad
#define SMEM_TOTAL 212512

__device__ __forceinline__ void mma16816(float* d, const uint32_t* a,
                                         uint32_t b0, uint32_t b1) {
  asm volatile(
    "mma.sync.aligned.m16n8k16.row.col.f32.bf16.bf16.f32 "
    "{%0,%1,%2,%3}, {%4,%5,%6,%7}, {%8,%9}, {%0,%1,%2,%3};"
    : "+f"(d[0]), "+f"(d[1]), "+f"(d[2]), "+f"(d[3])
    : "r"(a[0]), "r"(a[1]), "r"(a[2]), "r"(a[3]), "r"(b0), "r"(b1));
}
__device__ __forceinline__ uint32_t packhi(float2 v) {
  __nv_bfloat162 p(__float2bfloat16(v.x), __float2bfloat16(v.y));
  return *reinterpret_cast<uint32_t*>(&p);
}
__device__ __forceinline__ uint32_t packlo(float2 v) {
  float rx = v.x - __bfloat162float(__float2bfloat16(v.x));
  float ry = v.y - __bfloat162float(__float2bfloat16(v.y));
  __nv_bfloat162 p(__float2bfloat16(rx), __float2bfloat16(ry));
  return *reinterpret_cast<uint32_t*>(&p);
}
__device__ __forceinline__ float sigf(float v) {
  return __fdividef(1.0f, 1.0f + __expf(-v));
}
__device__ __forceinline__ float tanhfast(float v) {
  float av = fabsf(v), e = __expf(-2.0f * av);
  return copysignf(__fdividef(1.0f - e, 1.0f + e), v);
}

__device__ __forceinline__ void giphase(float (&Dp)[3][2][4], float (&gin)[8],
    const float* xc, const float* wih, int jA, int jB, int tg,
    float brA, float brB, float bzA, float bzB, float binA, float binB) {
  float gr[8], gz[8];
  #pragma unroll
  for (int e = 0; e < 8; e++) {
    int rh = (e >> 1) & 1;
    gr[e] = rh ? brB : brA; gz[e] = rh ? bzB : bzA; gin[e] = rh ? binB : binA;
  }
  #pragma unroll
  for (int i = 0; i < 6; i++) {
    float wrA = wih[jA*6+i],       wrB = wih[jB*6+i];
    float wzA = wih[(128+jA)*6+i], wzB = wih[(128+jB)*6+i];
    float wnA = wih[(256+jA)*6+i], wnB = wih[(256+jB)*6+i];
    #pragma unroll
    for (int e = 0; e < 8; e++) {
      int nt = e >> 2, rh = (e >> 1) & 1, cc = e & 1;
      float xv = xc[(nt*8 + tg*2 + cc)*6 + i];
      gr[e]  = fmaf(rh ? wrB : wrA, xv, gr[e]);
      gz[e]  = fmaf(rh ? wzB : wzA, xv, gz[e]);
      gin[e] = fmaf(rh ? wnB : wnA, xv, gin[e]);
    }
  }
  #pragma unroll
  for (int e = 0; e < 8; e++) {
    int nt = e >> 2, ei = ((e >> 1) & 1) * 2 + (e & 1);
    Dp[0][nt][ei] += gr[e]; Dp[1][nt][ei] += gz[e];
  }
}

template<bool G, bool C>
__device__ __forceinline__ void fused(float (&Dg)[3][2][4], float (&Dp)[3][2][4],
    const float (&gin)[8], float (&hC)[8], const uint32_t (&ahi)[3][8][4],
    char* sb, uint32_t hfG, uint32_t hfC, int w, int l, int tg, int grp,
    float bhnA, float bhnB) {
  if (G) {
    #pragma unroll
    for (int g = 0; g < 3; g++)
      #pragma unroll
      for (int nt = 0; nt < 2; nt++)
        #pragma unroll
        for (int r = 0; r < 4; r++) Dg[g][nt][r] = 0.0f;
  }
  #pragma unroll
  for (int kc = 0; kc < 8; kc++) {
    if (G) {
      uint2 b0f[2], b1f[2];
      #pragma unroll
      for (int nt = 0; nt < 2; nt++) {
        b0f[nt] = *(const uint2*)(sb + hfG + ((kc*2 + nt)*32 + l)*8);
        b1f[nt] = *(const uint2*)(sb + hfG + 4096 + ((kc*2 + nt)*32 + l)*8);
      }
      uint32_t alo[3][4];
      #pragma unroll
      for (int g = 0; g < 3; g++) {
        uint4 v = *(const uint4*)(sb + OFF_WLO + (((w*3 + g)*8 + kc)*32 + l)*16);
        alo[g][0] = v.x; alo[g][1] = v.y; alo[g][2] = v.z; alo[g][3] = v.w;
      }
      #pragma unroll
      for (int g = 0; g < 3; g++) {
        mma16816(Dg[g][0], ahi[g][kc], b0f[0].x, b0f[0].y);
        mma16816(Dg[g][1], ahi[g][kc], b0f[1].x, b0f[1].y);
      }
      #pragma unroll
      for (int g = 0; g < 3; g++) {
        mma16816(Dg[g][0], ahi[g][kc], b1f[0].x, b1f[0].y);
        mma16816(Dg[g][1], ahi[g][kc], b1f[1].x, b1f[1].y);
      }
      #pragma unroll
      for (int g = 0; g < 3; g++) {
        mma16816(Dg[g][0], alo[g], b0f[0].x, b0f[0].y);
        mma16816(Dg[g][1], alo[g], b0f[1].x, b0f[1].y);
      }
    }
    if (C) {
      const int e = kc, nt = e >> 2, rh = (e >> 1) & 1, cc = e & 1;
      const int ei = rh * 2 + cc;
      float rg = sigf(Dp[0][nt][ei]);
      float zg = sigf(Dp[1][nt][ei]);
      float ng = tanhfast(fmaf(rg, Dp[2][nt][ei] + (rh ? bhnB : bhnA), gin[e]));
      float h  = fmaf(zg, hC[e] - ng, ng);
      hC[e] = h;
      __nv_bfloat16 hi = __float2bfloat16(h);
      __nv_bfloat16 lo = __float2bfloat16(h - __bfloat162float(hi));
      uint32_t off = (uint32_t)(((w*2 + nt)*32 + (tg*2 + cc)*4 + (grp >> 1))*8
                    + rh*4 + (grp & 1)*2);
      *(__nv_bfloat16*)(sb + hfC + off) = hi;
      *(__nv_bfloat16*)(sb + hfC + 4096 + off) = lo;
    }
  }
}

__device__ __forceinline__ void headmma(float (&Da)[2][4], char* sb,
                                        uint32_t hfG, int w, int l) {
  #pragma unroll
  for (int nt = 0; nt < 2; nt++)
    #pragma unroll
    for (int r = 0; r < 4; r++) Da[nt][r] = 0.0f;
  #pragma unroll
  for (int kc = 0; kc < 8; kc++) {
    uint2 b0f[2], b1f[2];
    #pragma unroll
    for (int nt = 0; nt < 2; nt++) {
      b0f[nt] = *(const uint2*)(sb + hfG + ((kc*2 + nt)*32 + l)*8);
      b1f[nt] = *(const uint2*)(sb + hfG + 4096 + ((kc*2 + nt)*32 + l)*8);
    }
    uint4 hv = *(const uint4*)(sb + OFF_W1F + ((w*8 + kc)*32 + l)*16);
    uint4 lv = *(const uint4*)(sb + OFF_W1F + 32768 + ((w*8 + kc)*32 + l)*16);
    uint32_t ah[4] = { hv.x, hv.y, hv.z, hv.w };
    uint32_t al[4] = { lv.x, lv.y, lv.z, lv.w };
    #pragma unroll
    for (int nt = 0; nt < 2; nt++) {
      mma16816(Da[nt], ah, b0f[nt].x, b0f[nt].y);
      mma16816(Da[nt], ah, b1f[nt].x, b1f[nt].y);
      mma16816(Da[nt], al, b0f[nt].x, b0f[nt].y);
    }
  }
}

__global__ void __launch_bounds__(NT, 1)
gru_pipe_kernel(const float* __restrict__ history,
                const float* __restrict__ w_ih,
                const float* __restrict__ w_hh,
                const float* __restrict__ b_ih,
                const float* __restrict__ b_hh,
                const float* __restrict__ w1,
                const float* __restrict__ b1,
                const float* __restrict__ w2,
                const float* __restrict__ b2,
                float* __restrict__ out)
{
  extern __shared__ char sb[];
  const int tid = threadIdx.x;
  const int w = tid >> 5, l = tid & 31;
  const int grp = l >> 2, tg = l & 3;
  const int jA = w * 16 + grp, jB = jA + 8;
  const int row0 = blockIdx.x * 32;

  float* xsv = (float*)(sb + OFF_XS);
  float* wih = (float*)(sb + OFF_WIH);
  float* w2s = (float*)(sb + OFF_W2S);
  float* b2s = (float*)(sb + OFF_B2S);

  for (int idx = tid; idx < 384 * II; idx += NT) wih[idx] = w_ih[idx];
  for (int idx = tid; idx < II * HH; idx += NT)  w2s[idx] = w2[idx];
  if (tid < II) b2s[tid] = b2[tid];
  for (int idx = tid; idx < 4096; idx += NT)
    ((uint32_t*)(sb + OFF_HF))[idx] = 0u;

  // W_hh frags: hi regs, lo smem
  uint32_t ahi[3][8][4];
  #pragma unroll
  for (int g = 0; g < 3; g++)
    #pragma unroll
    for (int kc = 0; kc < 8; kc++) {
      int rA = g * HH + jA, rB = g * HH + jB, k0 = kc * 16 + tg * 2;
      float2 vA0 = *(const float2*)(w_hh + (size_t)rA * HH + k0);
      float2 vB0 = *(const float2*)(w_hh + (size_t)rB * HH + k0);
      float2 vA1 = *(const float2*)(w_hh + (size_t)rA * HH + k0 + 8);
      float2 vB1 = *(const float2*)(w_hh + (size_t)rB * HH + k0 + 8);
      ahi[g][kc][0] = packhi(vA0); ahi[g][kc][1] = packhi(vB0);
      ahi[g][kc][2] = packhi(vA1); ahi[g][kc][3] = packhi(vB1);
      uint4 lo = { packlo(vA0), packlo(vB0), packlo(vA1), packlo(vB1) };
      *(uint4*)(sb + OFF_WLO + (((w*3 + g)*8 + kc)*32 + l)*16) = lo;
    }
  // w1 frags hi/lo
  #pragma unroll
  for (int kc = 0; kc < 8; kc++) {
    int k0 = kc * 16 + tg * 2;
    float2 vA0 = *(const float2*)(w1 + (size_t)jA * HH + k0);
    float2 vB0 = *(const float2*)(w1 + (size_t)jB * HH + k0);
    float2 vA1 = *(const float2*)(w1 + (size_t)jA * HH + k0 + 8);
    float2 vB1 = *(const float2*)(w1 + (size_t)jB * HH + k0 + 8);
    uint4 hi = { packhi(vA0), packhi(vB0), packhi(vA1), packhi(vB1) };
    uint4 lo = { packlo(vA0), packlo(vB0), packlo(vA1), packlo(vB1) };
    *(uint4*)(sb + OFF_W1F + ((w*8 + kc)*32 + l)*16) = hi;
    *(uint4*)(sb + OFF_W1F + 32768 + ((w*8 + kc)*32 + l)*16) = lo;
  }
  // prologue x load: sub-tile 0, step 0, parity 0
  if (tid < 96) {
    int n = tid / 6, i = tid - n * 6;
    xsv[tid] = history[(size_t)(row0 + n) * (TT * II) + i];
  }

  const float brA  = b_ih[jA] + b_hh[jA],          brB  = b_ih[jB] + b_hh[jB];
  const float bzA  = b_ih[HH+jA] + b_hh[HH+jA],    bzB  = b_ih[HH+jB] + b_hh[HH+jB];
  const float binA = b_ih[2*HH+jA],                binB = b_ih[2*HH+jB];
  const float bhnA = b_hh[2*HH+jA],                bhnB = b_hh[2*HH+jB];
  const float b1A  = b1[jA],                       b1B  = b1[jB];

  float Dk0[3][2][4], Dk1[3][2][4], hr0[8], hr1[8];
  #pragma unroll
  for (int e = 0; e < 8; e++) { hr0[e] = 0.0f; hr1[e] = 0.0f; }
  __syncthreads();

  for (int k = 0; k <= 2 * NSTEP + 2; k++) {
    const int s = k & 1, sc = 1 - s;
    const int tmm = k >> 1, tc = (k - 1) >> 1, te = tc - 1;
    const bool doG = tmm < NSTEP;
    const bool doC = (tc >= 0) && (tc < NSTEP);
    const bool doH = (tmm > TT) && (tmm <= NSTEP);
    const bool doE = te >= TT;
    const uint32_t hfG = OFF_HF + (uint32_t)s * 8192;
    const uint32_t hfC = OFF_HF + (uint32_t)sc * 8192;

    if (doE) {   // w2 epilogue for (sc, te): AT[sc] -> xs + out
      if (tid < 96) {
        int n = tid / 6, i = tid - n * 6;
        const float* at = (const float*)(sb + OFF_AT + sc * 9216);
        float acc = b2s[i];
        const float* w2p = w2s + i * HH;
        #pragma unroll 8
        for (int kk = 0; kk < HH; kk++) acc = fmaf(at[kk*18 + n], w2p[kk], acc);
        xsv[(sc*2 + ((te + 1) & 1))*96 + tid] = acc;
        out[(size_t)(row0 + sc*16 + n)*(FUTN*II) + (size_t)(te - TT)*II + i] = acc;
      }
      __syncthreads();
    }
    {  // encoder x prefetch (one bracket ahead)
      int tl = tmm + s;
      if (tl < TT && tid < 96) {
        int n = tid / 6, i = tid - n * 6;
        xsv[(sc*2 + (tl & 1))*96 + tid] =
            history[(size_t)(row0 + sc*16 + n)*(TT*II) + (size_t)tl*II + i];
      }
    }
    const int par_c = (tc == TT) ? 1 : (tc & 1);
    const float* xc = xsv + (sc*2 + par_c) * 96;
    float gin[8];
    if (s == 0) {
      if (doC) giphase(Dk1, gin, xc, wih, jA, jB, tg, brA, brB, bzA, bzB, binA, binB);
      if (doG && doC)      fused<true,true >(Dk0, Dk1, gin, hr1, ahi, sb, hfG, hfC, w, l, tg, grp, bhnA, bhnB);
      else if (doG)        fused<true,false>(Dk0, Dk1, gin, hr1, ahi, sb, hfG, hfC, w, l, tg, grp, bhnA, bhnB);
      else if (doC)        fused<false,true>(Dk0, Dk1, gin, hr1, ahi, sb, hfG, hfC, w, l, tg, grp, bhnA, bhnB);
    } else {
      if (doC) giphase(Dk0, gin, xc, wih, jA, jB, tg, brA, brB, bzA, bzB, binA, binB);
      if (doG && doC)      fused<true,true >(Dk1, Dk0, gin, hr0, ahi, sb, hfG, hfC, w, l, tg, grp, bhnA, bhnB);
      else if (doG)        fused<true,false>(Dk1, Dk0, gin, hr0, ahi, sb, hfG, hfC, w, l, tg, grp, bhnA, bhnB);
      else if (doC)        fused<false,true>(Dk1, Dk0, gin, hr0, ahi, sb, hfG, hfC, w, l, tg, grp, bhnA, bhnB);
    }
    if (doH) {   // head for (s, tmm-1): HF_s holds h_{tmm-1}
      float Da[2][4];
      headmma(Da, sb, hfG, w, l);
      float* at = (float*)(sb + OFF_AT + s * 9216);
      #pragma unroll
      for (int nt = 0; nt < 2; nt++) {
        at[jA*18 + nt*8 + tg*2 + 0] = fmaxf(Da[nt][0] + b1A, 0.0f);
        at[jA*18 + nt*8 + tg*2 + 1] = fmaxf(Da[nt][1] + b1A, 0.0f);
        at[jB*18 + nt*8 + tg*2 + 0] = fmaxf(Da[nt][2] + b1B, 0.0f);
        at[jB*18 + nt*8 + tg*2 + 1] = fmaxf(Da[nt][3] + b1B, 0.0f);
      }
    }
    __syncthreads();
  }
}

extern "C" void kernel_launch(void* const* d_in, const int* in_sizes, int n_in,
                              void* d_out, int out_size) {
  const float* history = (const float*)d_in[0];
  const float* w_ih    = (const float*)d_in[1];
  const float* w_hh    = (const float*)d_in[2];
  const float* b_ih    = (const float*)d_in[3];
  const float* b_hh    = (const float*)d_in[4];
  const float* w1      = (const float*)d_in[5];
  const float* b1      = (const float*)d_in[6];
  const float* w2      = (const float*)d_in[7];
  const float* b2      = (const float*)d_in[8];
  float* out = (float*)d_out;

  cudaFuncSetAttribute(gru_pipe_kernel,
                       cudaFuncAttributeMaxDynamicSharedMemorySize, SMEM_TOTAL);
  gru_pipe_kernel<<<512, NT, SMEM_TOTAL>>>(
      history, w_ih, w_hh, b_ih, b_hh, w1, b1, w2, b2, out);
}

// round 10
// speedup vs baseline: 7.0728x; 1.3151x over previous
#include <cuda_runtime.h>
#include <cuda_fp16.h>
#include <cstdint>

// TrajectoryGRU, mma.sync fp16x2 (2-pass), 512 threads, two independent
// 16-row half-groups per CTA synchronized by named barriers. Grid 512.
// W_hh/w1 hi fragments in SMEM (fp16), h as fp16 hi+lo B-fragments.

#define TT    50
#define II    6
#define HH    128
#define FUTN  30
#define NSTEP 80
#define NT    512

#define OFF_WA   0        // W_hh frags [m8][g3][kc8][lane32] u4 = 98304
#define OFF_W1F  98304    // w1 frags [m8][kc8][lane32] u4 = 32768
#define OFF_HF   131072   // [hf2][h0 4096 | h1 4096] = 16384
#define OFF_AT   147456   // [hf2][16][136] f32 = 17408
#define OFF_XSE  164864   // [hf2][par2][96] f32 = 1536
#define OFF_XSD  166400   // [hf2][96] f32 = 768
#define OFF_WIH  167168   // [384][6] f32 = 9216
#define OFF_W2S  176384   // [6][128] f32 = 3072
#define OFF_B2S  179456   // [8] f32
#define SMEM_TOTAL 179520

__device__ __forceinline__ void mma16816(float* d, const uint32_t* a,
                                         uint32_t b0, uint32_t b1) {
  asm volatile(
    "mma.sync.aligned.m16n8k16.row.col.f32.f16.f16.f32 "
    "{%0,%1,%2,%3}, {%4,%5,%6,%7}, {%8,%9}, {%0,%1,%2,%3};"
    : "+f"(d[0]), "+f"(d[1]), "+f"(d[2]), "+f"(d[3])
    : "r"(a[0]), "r"(a[1]), "r"(a[2]), "r"(a[3]), "r"(b0), "r"(b1));
}
__device__ __forceinline__ uint32_t packh2(float2 v) {
  __half2 p(__float2half_rn(v.x), __float2half_rn(v.y));
  return *reinterpret_cast<uint32_t*>(&p);
}
__device__ __forceinline__ float sigf(float v) {
  return __fdividef(1.0f, 1.0f + __expf(-v));
}
__device__ __forceinline__ float tanhfast(float v) {
  float av = fabsf(v), e = __expf(-2.0f * av);
  return copysignf(__fdividef(1.0f - e, 1.0f + e), v);
}

__device__ __forceinline__ void gi_add(float (&D)[3][2][4], float (&gin)[8],
    const float* xc, const float* wih, int jA, int jB, int tg,
    float brA, float brB, float bzA, float bzB, float binA, float binB,
    float bhnA, float bhnB) {
  #pragma unroll
  for (int nt = 0; nt < 2; nt++)
    #pragma unroll
    for (int cc = 0; cc < 2; cc++) {
      const float* xp = xc + (nt * 8 + tg * 2 + cc) * 6;
      float x0 = xp[0], x1 = xp[1], x2 = xp[2], x3 = xp[3], x4 = xp[4], x5 = xp[5];
      #pragma unroll
      for (int rh = 0; rh < 2; rh++) {
        int j = rh ? jB : jA;
        const float* wr = wih + j * 6;
        const float* wz = wih + (128 + j) * 6;
        const float* wn = wih + (256 + j) * 6;
        float gr = rh ? brB : brA, gz = rh ? bzB : bzA, gn = rh ? binB : binA;
        gr = fmaf(wr[0],x0,fmaf(wr[1],x1,fmaf(wr[2],x2,fmaf(wr[3],x3,fmaf(wr[4],x4,fmaf(wr[5],x5,gr))))));
        gz = fmaf(wz[0],x0,fmaf(wz[1],x1,fmaf(wz[2],x2,fmaf(wz[3],x3,fmaf(wz[4],x4,fmaf(wz[5],x5,gz))))));
        gn = fmaf(wn[0],x0,fmaf(wn[1],x1,fmaf(wn[2],x2,fmaf(wn[3],x3,fmaf(wn[4],x4,fmaf(wn[5],x5,gn))))));
        int ei = rh * 2 + cc;
        D[0][nt][ei] += gr;
        D[1][nt][ei] += gz;
        D[2][nt][ei] += rh ? bhnB : bhnA;
        gin[nt * 4 + rh * 2 + cc] = gn;
      }
    }
}

__global__ void __launch_bounds__(NT, 1)
gru_h2_kernel(const float* __restrict__ history,
              const float* __restrict__ w_ih,
              const float* __restrict__ w_hh,
              const float* __restrict__ b_ih,
              const float* __restrict__ b_hh,
              const float* __restrict__ w1,
              const float* __restrict__ b1,
              const float* __restrict__ w2,
              const float* __restrict__ b2,
              float* __restrict__ out)
{
  extern __shared__ char sb[];
  const int tid = threadIdx.x;
  const int w = tid >> 5, l = tid & 31;
  const int grp = l >> 2, tg = l & 3;
  const int hf = w >> 3, w8 = w & 7;
  const int tidh = tid - hf * 256;
  const int jA = w8 * 16 + grp, jB = jA + 8;
  const int row0 = blockIdx.x * 32 + hf * 16;   // this half's first batch row
  const uint32_t hfHF = OFF_HF + (uint32_t)hf * 8192;

  float* xseP = (float*)(sb + OFF_XSE);
  float* xsdP = (float*)(sb + OFF_XSD);
  float* wih  = (float*)(sb + OFF_WIH);
  float* w2s  = (float*)(sb + OFF_W2S);
  float* b2s  = (float*)(sb + OFF_B2S);
  float* atb  = (float*)(sb + OFF_AT) + hf * 2176;   // [16][136]

  // ---------- init ----------
  for (int idx = tid; idx < 384 * 6; idx += NT) wih[idx] = w_ih[idx];
  for (int idx = tid; idx < 6 * 128; idx += NT) w2s[idx] = w2[idx];
  if (tid < 6) b2s[tid] = b2[tid];
  for (int idx = tid; idx < 4096; idx += NT)
    ((uint32_t*)(sb + OFF_HF))[idx] = 0u;

  if (hf == 0) {   // warps 0-7: W_hh fp16 A-fragments
    #pragma unroll
    for (int g = 0; g < 3; g++)
      #pragma unroll
      for (int kc = 0; kc < 8; kc++) {
        int rA = g * HH + jA, rB = g * HH + jB, k0 = kc * 16 + tg * 2;
        float2 a0 = *(const float2*)(w_hh + (size_t)rA * HH + k0);
        float2 b0 = *(const float2*)(w_hh + (size_t)rB * HH + k0);
        float2 a1 = *(const float2*)(w_hh + (size_t)rA * HH + k0 + 8);
        float2 b1v= *(const float2*)(w_hh + (size_t)rB * HH + k0 + 8);
        uint4 f = { packh2(a0), packh2(b0), packh2(a1), packh2(b1v) };
        *(uint4*)(sb + OFF_WA + (((w8 * 3 + g) * 8 + kc) * 32 + l) * 16) = f;
      }
  } else {         // warps 8-15: w1 fp16 A-fragments
    #pragma unroll
    for (int kc = 0; kc < 8; kc++) {
      int k0 = kc * 16 + tg * 2;
      float2 a0 = *(const float2*)(w1 + (size_t)jA * HH + k0);
      float2 b0 = *(const float2*)(w1 + (size_t)jB * HH + k0);
      float2 a1 = *(const float2*)(w1 + (size_t)jA * HH + k0 + 8);
      float2 b1v= *(const float2*)(w1 + (size_t)jB * HH + k0 + 8);
      uint4 f = { packh2(a0), packh2(b0), packh2(a1), packh2(b1v) };
      *(uint4*)(sb + OFF_W1F + ((w8 * 8 + kc) * 32 + l) * 16) = f;
    }
  }
  if (tidh < 96) {   // x(0)
    int n = tidh / 6, i = tidh - n * 6;
    xseP[(hf * 2 + 0) * 96 + tidh] = history[(size_t)(row0 + n) * (TT * II) + i];
  }

  const float brA  = b_ih[jA] + b_hh[jA],         brB  = b_ih[jB] + b_hh[jB];
  const float bzA  = b_ih[HH+jA] + b_hh[HH+jA],   bzB  = b_ih[HH+jB] + b_hh[HH+jB];
  const float binA = b_ih[2*HH+jA],               binB = b_ih[2*HH+jB];
  const float bhnA = b_hh[2*HH+jA],               bhnB = b_hh[2*HH+jB];
  const float b1A  = b1[jA],                      b1B  = b1[jB];

  float hreg[8];
  #pragma unroll
  for (int e = 0; e < 8; e++) hreg[e] = 0.0f;
  __syncthreads();

  #define BARH() asm volatile("bar.sync %0, 256;" :: "r"(hf + 1) : "memory")

  for (int t = 0; t <= NSTEP; t++) {
    const bool doGH = t < NSTEP;
    const bool doHd = t > TT;

    // encoder x prefetch
    if (t + 1 < TT && tidh < 96) {
      int n = tidh / 6, i = tidh - n * 6;
      xseP[(hf * 2 + ((t + 1) & 1)) * 96 + tidh] =
          history[(size_t)(row0 + n) * (TT * II) + (size_t)(t + 1) * 6 + i];
    }

    float D[3][2][4], gin[8];
    #pragma unroll
    for (int g = 0; g < 3; g++)
      #pragma unroll
      for (int nt = 0; nt < 2; nt++)
        #pragma unroll
        for (int r = 0; r < 4; r++) D[g][nt][r] = 0.0f;

    if (doGH && t <= TT) {   // early gi (encoder + first decoder step)
      int par = (t < TT) ? (t & 1) : 1;
      gi_add(D, gin, xseP + (hf * 2 + par) * 96, wih, jA, jB, tg,
             brA, brB, bzA, bzB, binA, binB, bhnA, bhnB);
    }

    if (doGH) {   // GH mma: 2 passes (h0, h1)
      #pragma unroll
      for (int kc = 0; kc < 8; kc++) {
        uint2 b0f[2], b1f[2];
        #pragma unroll
        for (int nt = 0; nt < 2; nt++) {
          b0f[nt] = *(const uint2*)(sb + hfHF + ((kc*2 + nt)*32 + l)*8);
          b1f[nt] = *(const uint2*)(sb + hfHF + 4096 + ((kc*2 + nt)*32 + l)*8);
        }
        uint32_t A[3][4];
        #pragma unroll
        for (int g = 0; g < 3; g++) {
          uint4 v = *(const uint4*)(sb + OFF_WA + (((w8*3 + g)*8 + kc)*32 + l)*16);
          A[g][0] = v.x; A[g][1] = v.y; A[g][2] = v.z; A[g][3] = v.w;
        }
        #pragma unroll
        for (int g = 0; g < 3; g++) {
          mma16816(D[g][0], A[g], b0f[0].x, b0f[0].y);
          mma16816(D[g][1], A[g], b0f[1].x, b0f[1].y);
        }
        #pragma unroll
        for (int g = 0; g < 3; g++) {
          mma16816(D[g][0], A[g], b1f[0].x, b1f[0].y);
          mma16816(D[g][1], A[g], b1f[1].x, b1f[1].y);
        }
      }
    }
    if (doHd) {   // head mma on h_{t-1} (same HF) -> AT
      float Da[2][4];
      #pragma unroll
      for (int nt = 0; nt < 2; nt++)
        #pragma unroll
        for (int r = 0; r < 4; r++) Da[nt][r] = 0.0f;
      #pragma unroll
      for (int kc = 0; kc < 8; kc++) {
        uint2 b0f[2], b1f[2];
        #pragma unroll
        for (int nt = 0; nt < 2; nt++) {
          b0f[nt] = *(const uint2*)(sb + hfHF + ((kc*2 + nt)*32 + l)*8);
          b1f[nt] = *(const uint2*)(sb + hfHF + 4096 + ((kc*2 + nt)*32 + l)*8);
        }
        uint4 v = *(const uint4*)(sb + OFF_W1F + ((w8*8 + kc)*32 + l)*16);
        uint32_t A[4] = { v.x, v.y, v.z, v.w };
        #pragma unroll
        for (int nt = 0; nt < 2; nt++) {
          mma16816(Da[nt], A, b0f[nt].x, b0f[nt].y);
          mma16816(Da[nt], A, b1f[nt].x, b1f[nt].y);
        }
      }
      #pragma unroll
      for (int nt = 0; nt < 2; nt++)
        #pragma unroll
        for (int cc = 0; cc < 2; cc++) {
          int n = nt * 8 + tg * 2 + cc;
          atb[n * 136 + jA] = fmaxf(Da[nt][cc]     + b1A, 0.0f);
          atb[n * 136 + jB] = fmaxf(Da[nt][2 + cc] + b1B, 0.0f);
        }
    }
    BARH();   // HF reads done; AT ready

    if (doHd) {
      if (tidh < 96) {   // w2 epilogue -> x_t, out pred (t-51)
        int n = tidh / 6, i = tidh - n * 6;
        const float4* a4 = (const float4*)(atb + n * 136);
        const float4* w4 = (const float4*)(w2s + i * 128);
        float acc = b2s[i];
        #pragma unroll 8
        for (int k4 = 0; k4 < 32; k4++) {
          float4 a = a4[k4], ww = w4[k4];
          acc = fmaf(a.x, ww.x, fmaf(a.y, ww.y, fmaf(a.z, ww.z, fmaf(a.w, ww.w, acc))));
        }
        if (t < NSTEP) xsdP[hf * 96 + tidh] = acc;
        out[(size_t)(row0 + n) * (FUTN * II) + (size_t)(t - TT - 1) * 6 + i] = acc;
      }
      BARH();   // xs_dec ready
      if (doGH)
        gi_add(D, gin, xsdP + hf * 96, wih, jA, jB, tg,
               brA, brB, bzA, bzB, binA, binB, bhnA, bhnB);
    }

    if (doGH) {   // combine -> h_t, write HF fp16 hi/lo
      #pragma unroll
      for (int e = 0; e < 8; e++) {
        int nt = e >> 2, rh = (e >> 1) & 1, cc = e & 1, ei = rh * 2 + cc;
        float r = sigf(D[0][nt][ei]);
        float z = sigf(D[1][nt][ei]);
        float n = tanhfast(fmaf(r, D[2][nt][ei], gin[e]));
        float h = fmaf(z, hreg[e] - n, n);
        hreg[e] = h;
        __half h0 = __float2half_rn(h);
        __half h1 = __float2half_rn(h - __half2float(h0));
        uint32_t off = (uint32_t)(((w8*2 + nt)*32 + (tg*2 + cc)*4 + (grp >> 1))*8
                      + rh*4 + (grp & 1)*2);
        *(__half*)(sb + hfHF + off) = h0;
        *(__half*)(sb + hfHF + 4096 + off) = h1;
      }
    }
    BARH();   // HF(h_t) published
  }
  #undef BARH
}

extern "C" void kernel_launch(void* const* d_in, const int* in_sizes, int n_in,
                              void* d_out, int out_size) {
  const float* history = (const float*)d_in[0];
  const float* w_ih    = (const float*)d_in[1];
  const float* w_hh    = (const float*)d_in[2];
  const float* b_ih    = (const float*)d_in[3];
  const float* b_hh    = (const float*)d_in[4];
  const float* w1      = (const float*)d_in[5];
  const float* b1      = (const float*)d_in[6];
  const float* w2      = (const float*)d_in[7];
  const float* b2      = (const float*)d_in[8];
  float* out = (float*)d_out;

  cudaFuncSetAttribute(gru_h2_kernel,
                       cudaFuncAttributeMaxDynamicSharedMemorySize, SMEM_TOTAL);
  gru_h2_kernel<<<512, NT, SMEM_TOTAL>>>(
      history, w_ih, w_hh, b_ih, b_hh, w1, b1, w2, b2, out);
}

// round 11
// speedup vs baseline: 7.2479x; 1.0248x over previous
#include <cuda_runtime.h>
#include <cuda_fp16.h>
#include <cstdint>

// TrajectoryGRU: producer/consumer warp-specialized fp16x2 mma pipeline.
// 512 thr: warps 0-7 (M) = all HMMA, warps 8-15 (C) = gi + activations + w2.
// 32 rows/CTA as two 16-row halves forming a 2-stage pipeline; 2 named
// barriers per step. D: M->C via smem; h: C->M via HF fragment buffer.

#define NT 512
#define OFF_WZN 0        // W_hh z/n A-frags [jt8][2][kc8][l32] u4 = 65536
#define OFF_W1F 65536    // w1 A-frags [mt8][kc8][l32] u4 = 32768
#define OFF_HF  98304    // [h2][512 slots x 16B {hi2,lo2}] = 16384
#define OFF_DG  114688   // [h2][3*16*132] f32 = 50688
#define OFF_AT  165376   // [h2][16*132] f32 = 16896
#define OFF_XSE 182272   // [h2][par2][96] f32 = 1536
#define OFF_XSD 183808   // [h2][96] f32 = 768
#define OFF_W2  184576   // [6][128] f32 = 3072
#define SMEM_TOTAL 187648

__device__ __forceinline__ void mma16816(float* d, const uint32_t* a,
                                         uint32_t b0, uint32_t b1) {
  asm volatile(
    "mma.sync.aligned.m16n8k16.row.col.f32.f16.f16.f32 "
    "{%0,%1,%2,%3}, {%4,%5,%6,%7}, {%8,%9}, {%0,%1,%2,%3};"
    : "+f"(d[0]), "+f"(d[1]), "+f"(d[2]), "+f"(d[3])
    : "r"(a[0]), "r"(a[1]), "r"(a[2]), "r"(a[3]), "r"(b0), "r"(b1));
}
__device__ __forceinline__ uint32_t packh2(float2 v) {
  __half2 p(__float2half_rn(v.x), __float2half_rn(v.y));
  return *reinterpret_cast<uint32_t*>(&p);
}
__device__ __forceinline__ float sigf(float v) {
  return __fdividef(1.0f, 1.0f + __expf(-v));
}
__device__ __forceinline__ float tanhfast(float v) {
  float av = fabsf(v), e = __expf(-2.0f * av);
  return copysignf(__fdividef(1.0f - e, 1.0f + e), v);
}
#define BARX(id, n) asm volatile("bar.sync %0, %1;" :: "r"(id), "r"(n) : "memory")

__global__ void __launch_bounds__(NT, 1)
gru_ws_kernel(const float* __restrict__ history, const float* __restrict__ w_ih,
              const float* __restrict__ w_hh, const float* __restrict__ b_ih,
              const float* __restrict__ b_hh, const float* __restrict__ w1,
              const float* __restrict__ b1, const float* __restrict__ w2,
              const float* __restrict__ b2, float* __restrict__ out)
{
  extern __shared__ char sb[];
  const int tid = threadIdx.x, w = tid >> 5, l = tid & 31;
  const int grp = l >> 2, tg = l & 3;
  const int row0 = blockIdx.x * 32;
  const bool isM = w < 8;

  float* w2s = (float*)(sb + OFF_W2);
  for (int i = tid; i < 768; i += NT) w2s[i] = w2[i];
  for (int i = tid; i < 4096; i += NT) ((uint32_t*)(sb + OFF_HF))[i] = 0u;
  if (tid < 192) {   // x(0) for both halves, parity 0
    int hh = tid / 96, idx = tid - hh * 96, n = idx / 6, i = idx - n * 6;
    ((float*)(sb + OFF_XSE))[hh * 192 + idx] =
        history[(size_t)(row0 + hh * 16 + n) * 300 + i];
  }

  // ---------------- role-specific register init ----------------
  uint32_t Ar[8][4];                 // M: r-gate W_hh frags
  float b1A = 0.f, b1B = 0.f;
  float wg[3][2][6], brv[2], bzv[2], binv[2], bhnv[2], b2r = 0.f;
  float hreg[2][4][2];
  int c = 0, ng = 0, jj = 0;

  if (isM) {
    const int mw = w, jA = mw * 16 + grp, jB = jA + 8;
    #pragma unroll
    for (int kc = 0; kc < 8; kc++) {
      int k0 = kc * 16 + tg * 2;
      Ar[kc][0] = packh2(*(const float2*)(w_hh + (size_t)jA * 128 + k0));
      Ar[kc][1] = packh2(*(const float2*)(w_hh + (size_t)jB * 128 + k0));
      Ar[kc][2] = packh2(*(const float2*)(w_hh + (size_t)jA * 128 + k0 + 8));
      Ar[kc][3] = packh2(*(const float2*)(w_hh + (size_t)jB * 128 + k0 + 8));
      #pragma unroll
      for (int g = 1; g < 3; g++) {
        int rA = g * 128 + jA, rB = g * 128 + jB;
        uint4 f = { packh2(*(const float2*)(w_hh + (size_t)rA * 128 + k0)),
                    packh2(*(const float2*)(w_hh + (size_t)rB * 128 + k0)),
                    packh2(*(const float2*)(w_hh + (size_t)rA * 128 + k0 + 8)),
                    packh2(*(const float2*)(w_hh + (size_t)rB * 128 + k0 + 8)) };
        *(uint4*)(sb + OFF_WZN + (((mw * 2 + (g - 1)) * 8 + kc) * 32 + l) * 16) = f;
      }
      uint4 f1 = { packh2(*(const float2*)(w1 + (size_t)jA * 128 + k0)),
                   packh2(*(const float2*)(w1 + (size_t)jB * 128 + k0)),
                   packh2(*(const float2*)(w1 + (size_t)jA * 128 + k0 + 8)),
                   packh2(*(const float2*)(w1 + (size_t)jB * 128 + k0 + 8)) };
      *(uint4*)(sb + OFF_W1F + ((mw * 8 + kc) * 32 + l) * 16) = f1;
    }
    b1A = b1[jA]; b1B = b1[jB];
  } else {
    c = tid - 256; ng = c >> 6; jj = (c & 63) * 2;
    #pragma unroll
    for (int jp = 0; jp < 2; jp++) {
      int j = jj + jp;
      #pragma unroll
      for (int g = 0; g < 3; g++)
        #pragma unroll
        for (int i = 0; i < 6; i++)
          wg[g][jp][i] = w_ih[(size_t)(g * 128 + j) * 6 + i];
      brv[jp]  = b_ih[j] + b_hh[j];
      bzv[jp]  = b_ih[128 + j] + b_hh[128 + j];
      binv[jp] = b_ih[256 + j];
      bhnv[jp] = b_hh[256 + j];
    }
    if (c < 192) b2r = b2[(c % 96) % 6];
    #pragma unroll
    for (int h = 0; h < 2; h++)
      #pragma unroll
      for (int q = 0; q < 4; q++) { hreg[h][q][0] = 0.f; hreg[h][q][1] = 0.f; }
  }
  __syncthreads();

  // ================= main loops =================
  if (isM) {
    const int mw = w;
    for (int t = 0; t <= 80; t++) {
      const bool doG = t < 80, doH = t > 50;
      #pragma unroll 1
      for (int h = 0; h < 2; h++) {
        float D[3][2][4], Da[2][4];
        if (doG) {
          #pragma unroll
          for (int g = 0; g < 3; g++)
            #pragma unroll
            for (int nt = 0; nt < 2; nt++)
              #pragma unroll
              for (int r = 0; r < 4; r++) D[g][nt][r] = 0.f;
        }
        if (doH) {
          #pragma unroll
          for (int nt = 0; nt < 2; nt++)
            #pragma unroll
            for (int r = 0; r < 4; r++) Da[nt][r] = 0.f;
        }
        const char* hfb = sb + OFF_HF + h * 8192;
        #pragma unroll
        for (int kc = 0; kc < 8; kc++) {
          uint4 v0 = *(const uint4*)(hfb + ((kc * 2 + 0) * 32 + l) * 16);
          uint4 v1 = *(const uint4*)(hfb + ((kc * 2 + 1) * 32 + l) * 16);
          if (doG) {
            uint4 za = *(const uint4*)(sb + OFF_WZN + ((mw * 16 + kc) * 32 + l) * 16);
            uint4 na = *(const uint4*)(sb + OFF_WZN + ((mw * 16 + 8 + kc) * 32 + l) * 16);
            uint32_t Az[4] = { za.x, za.y, za.z, za.w };
            uint32_t An[4] = { na.x, na.y, na.z, na.w };
            mma16816(D[0][0], Ar[kc], v0.x, v0.y);
            mma16816(D[0][1], Ar[kc], v1.x, v1.y);
            mma16816(D[1][0], Az, v0.x, v0.y);
            mma16816(D[1][1], Az, v1.x, v1.y);
            mma16816(D[2][0], An, v0.x, v0.y);
            mma16816(D[2][1], An, v1.x, v1.y);
            mma16816(D[0][0], Ar[kc], v0.z, v0.w);
            mma16816(D[0][1], Ar[kc], v1.z, v1.w);
            mma16816(D[1][0], Az, v0.z, v0.w);
            mma16816(D[1][1], Az, v1.z, v1.w);
            mma16816(D[2][0], An, v0.z, v0.w);
            mma16816(D[2][1], An, v1.z, v1.w);
          }
          if (doH) {
            uint4 ha = *(const uint4*)(sb + OFF_W1F + ((mw * 8 + kc) * 32 + l) * 16);
            uint32_t A1[4] = { ha.x, ha.y, ha.z, ha.w };
            mma16816(Da[0], A1, v0.x, v0.y);
            mma16816(Da[1], A1, v1.x, v1.y);
            mma16816(Da[0], A1, v0.z, v0.w);
            mma16816(Da[1], A1, v1.z, v1.w);
          }
        }
        if (doG) {
          float* dg = (float*)(sb + OFF_DG) + h * 6336;
          #pragma unroll
          for (int g = 0; g < 3; g++)
            #pragma unroll
            for (int nt = 0; nt < 2; nt++)
              #pragma unroll
              for (int rh = 0; rh < 2; rh++)
                #pragma unroll
                for (int cc = 0; cc < 2; cc++)
                  dg[(g * 16 + nt * 8 + tg * 2 + cc) * 132 + mw * 16 + rh * 8 + grp]
                      = D[g][nt][rh * 2 + cc];
        }
        if (doH) {
          float* at = (float*)(sb + OFF_AT) + h * 2112;
          #pragma unroll
          for (int nt = 0; nt < 2; nt++)
            #pragma unroll
            for (int rh = 0; rh < 2; rh++)
              #pragma unroll
              for (int cc = 0; cc < 2; cc++)
                at[(nt * 8 + tg * 2 + cc) * 132 + mw * 16 + rh * 8 + grp] =
                    fmaxf(Da[nt][rh * 2 + cc] + (rh ? b1B : b1A), 0.f);
        }
        BARX(h + 1, 512);
      }
    }
  } else {
    for (int t = 0; t <= 80; t++) {
      #pragma unroll 1
      for (int h = 0; h < 2; h++) {
        BARX(h + 1, 512);
        if (t > 50) {           // w2 epilogue for this half (aT ready)
          if (c >= h * 96 && c < h * 96 + 96) {
            int idx = c - h * 96, n = idx / 6, i = idx - n * 6;
            const float4* a4 =
                (const float4*)((float*)(sb + OFF_AT) + h * 2112 + n * 132);
            const float4* wv = (const float4*)(w2s + i * 128);
            float acc = b2r;
            #pragma unroll 8
            for (int k4 = 0; k4 < 32; k4++) {
              float4 a = a4[k4], ww = wv[k4];
              acc = fmaf(a.x, ww.x, fmaf(a.y, ww.y,
                    fmaf(a.z, ww.z, fmaf(a.w, ww.w, acc))));
            }
            ((float*)(sb + OFF_XSD))[h * 96 + idx] = acc;
            out[(size_t)(row0 + h * 16 + n) * 180 + (size_t)(t - 51) * 6 + i] = acc;
          }
          BARX(3, 256);
        }
        if (t < 80) {           // gi + combine -> h_t
          const float* xq =
              (t < 50) ? (const float*)(sb + OFF_XSE) + (h * 2 + (t & 1)) * 96
            : (t == 50) ? (const float*)(sb + OFF_XSE) + (h * 2 + 1) * 96
            : (const float*)(sb + OFF_XSD) + h * 96;
          float* dg = (float*)(sb + OFF_DG) + h * 6336;
          #pragma unroll
          for (int q = 0; q < 4; q++) {
            int n = ng * 4 + q;
            const float* xp = xq + n * 6;
            float x0 = xp[0], x1 = xp[1], x2 = xp[2],
                  x3 = xp[3], x4 = xp[4], x5 = xp[5];
            float2 Dr = *(const float2*)(dg + n * 132 + jj);
            float2 Dz = *(const float2*)(dg + (16 + n) * 132 + jj);
            float2 Dn = *(const float2*)(dg + (32 + n) * 132 + jj);
            float hv[2];
            #pragma unroll
            for (int jp = 0; jp < 2; jp++) {
              float gr = brv[jp], gz = bzv[jp], gn = binv[jp];
              gr = fmaf(wg[0][jp][0], x0, fmaf(wg[0][jp][1], x1, fmaf(wg[0][jp][2], x2,
                   fmaf(wg[0][jp][3], x3, fmaf(wg[0][jp][4], x4, fmaf(wg[0][jp][5], x5, gr))))));
              gz = fmaf(wg[1][jp][0], x0, fmaf(wg[1][jp][1], x1, fmaf(wg[1][jp][2], x2,
                   fmaf(wg[1][jp][3], x3, fmaf(wg[1][jp][4], x4, fmaf(wg[1][jp][5], x5, gz))))));
              gn = fmaf(wg[2][jp][0], x0, fmaf(wg[2][jp][1], x1, fmaf(wg[2][jp][2], x2,
                   fmaf(wg[2][jp][3], x3, fmaf(wg[2][jp][4], x4, fmaf(wg[2][jp][5], x5, gn))))));
              float r = sigf(gr + (jp ? Dr.y : Dr.x));
              float z = sigf(gz + (jp ? Dz.y : Dz.x));
              float nn = tanhfast(fmaf(r, (jp ? Dn.y : Dn.x) + bhnv[jp], gn));
              float hh = fmaf(z, hreg[h][q][jp] - nn, nn);
              hreg[h][q][jp] = hh;
              hv[jp] = hh;
            }
            __half a0 = __float2half_rn(hv[0]), a1 = __float2half_rn(hv[1]);
            __half2 hi2(a0, a1);
            __half2 lo2(__float2half_rn(hv[0] - __half2float(a0)),
                        __float2half_rn(hv[1] - __half2float(a1)));
            uint32_t slot = (uint32_t)((jj >> 4) * 64 + (n >> 3) * 32
                          + (n & 7) * 4 + ((jj & 7) >> 1));
            char* p = sb + OFF_HF + h * 8192 + slot * 16 + ((jj >> 3) & 1) * 4;
            *(uint32_t*)p       = *(uint32_t*)&hi2;
            *(uint32_t*)(p + 8) = *(uint32_t*)&lo2;
          }
        }
        if (h == 1 && t + 1 < 50 && c < 192) {   // encoder x prefetch
          int hh = c / 96, idx = c - hh * 96, n = idx / 6, i = idx - n * 6;
          ((float*)(sb + OFF_XSE))[(hh * 2 + ((t + 1) & 1)) * 96 + idx] =
              history[(size_t)(row0 + hh * 16 + n) * 300 + (size_t)(t + 1) * 6 + i];
        }
      }
    }
  }
}

extern "C" void kernel_launch(void* const* d_in, const int* in_sizes, int n_in,
                              void* d_out, int out_size) {
  const float* history = (const float*)d_in[0];
  const float* w_ih    = (const float*)d_in[1];
  const float* w_hh    = (const float*)d_in[2];
  const float* b_ih    = (const float*)d_in[3];
  const float* b_hh    = (const float*)d_in[4];
  const float* w1      = (const float*)d_in[5];
  const float* b1      = (const float*)d_in[6];
  const float* w2      = (const float*)d_in[7];
  const float* b2      = (const float*)d_in[8];
  float* out = (float*)d_out;

  cudaFuncSetAttribute(gru_ws_kernel,
                       cudaFuncAttributeMaxDynamicSharedMemorySize, SMEM_TOTAL);
  gru_ws_kernel<<<512, NT, SMEM_TOTAL>>>(
      history, w_ih, w_hh, b_ih, b_hh, w1, b1, w2, b2, out);
}